// round 1
// baseline (speedup 1.0000x reference)
#include <cuda_runtime.h>
#include <math.h>

#define DIMM 768
#define HEADS 16
#define DH 48
#define NB 8
#define NSEQ 1024
#define ROWS 8192            // NB*NSEQ
#define QKVC 2304            // 3*DIMM
#define SLICE_SZ 49152       // NSEQ*DH
#define HEAD_BLK 786432      // HEADS*NSEQ*DH
#define THIRD 6291456        // NB*HEAD_BLK
#define ATT_SCALE 0.14433756729740643f  // 48^-0.5

// scratch (allocation-free rule: __device__ globals)
__device__ float g_qkv[ROWS * QKVC];   // ~75.5 MB
__device__ float g_ctx[ROWS * DIMM];   // ~25.2 MB

// ---------------------------------------------------------------------------
// Classic fp32 SGEMM: C[M,Nc] = A[M,K] @ B[K,Nc] (+bias). BM=BN=128, BK=8,
// 256 threads, 8x8 per-thread microtile. All dims divisible (checked host-side
// by construction: M=8192, Nc in {2304,768}, K=768).
// ---------------------------------------------------------------------------
__global__ __launch_bounds__(256)
void sgemm_kernel(const float* __restrict__ A, const float* __restrict__ Bm,
                  const float* __restrict__ bias, float* __restrict__ C,
                  int M, int Nc, int K)
{
    __shared__ float As[8][128];   // transposed A tile
    __shared__ float Bs[8][128];

    const int tid = threadIdx.x;
    const int tx = tid & 15;
    const int ty = tid >> 4;
    const int rowBase = blockIdx.y << 7;
    const int colBase = blockIdx.x << 7;

    const int aRow = tid >> 1;          // 0..127
    const int aK   = (tid & 1) << 2;    // 0 or 4
    const int bRow = tid >> 5;          // 0..7
    const int bCol = (tid & 31) << 2;   // 0..124

    const float* Ap = A + (long)(rowBase + aRow) * K + aK;
    const float* Bp = Bm + (long)bRow * Nc + colBase + bCol;

    float acc[8][8];
    #pragma unroll
    for (int i = 0; i < 8; ++i)
        #pragma unroll
        for (int j = 0; j < 8; ++j) acc[i][j] = 0.f;

    for (int k0 = 0; k0 < K; k0 += 8) {
        float4 av = *(const float4*)(Ap + k0);
        float4 bv = *(const float4*)(Bp + (long)k0 * Nc);
        __syncthreads();
        As[aK + 0][aRow] = av.x;
        As[aK + 1][aRow] = av.y;
        As[aK + 2][aRow] = av.z;
        As[aK + 3][aRow] = av.w;
        *(float4*)&Bs[bRow][bCol] = bv;
        __syncthreads();
        #pragma unroll
        for (int k = 0; k < 8; ++k) {
            float ar[8], br[8];
            *(float4*)&ar[0] = *(const float4*)&As[k][ty << 3];
            *(float4*)&ar[4] = *(const float4*)&As[k][(ty << 3) + 4];
            *(float4*)&br[0] = *(const float4*)&Bs[k][tx << 3];
            *(float4*)&br[4] = *(const float4*)&Bs[k][(tx << 3) + 4];
            #pragma unroll
            for (int i = 0; i < 8; ++i)
                #pragma unroll
                for (int j = 0; j < 8; ++j)
                    acc[i][j] += ar[i] * br[j];
        }
    }

    float bl[8];
    if (bias != nullptr) {
        *(float4*)&bl[0] = *(const float4*)(bias + colBase + (tx << 3));
        *(float4*)&bl[4] = *(const float4*)(bias + colBase + (tx << 3) + 4);
    } else {
        #pragma unroll
        for (int j = 0; j < 8; ++j) bl[j] = 0.f;
    }

    #pragma unroll
    for (int i = 0; i < 8; ++i) {
        long r = rowBase + (ty << 3) + i;
        float4 o0, o1;
        o0.x = acc[i][0] + bl[0]; o0.y = acc[i][1] + bl[1];
        o0.z = acc[i][2] + bl[2]; o0.w = acc[i][3] + bl[3];
        o1.x = acc[i][4] + bl[4]; o1.y = acc[i][5] + bl[5];
        o1.z = acc[i][6] + bl[6]; o1.w = acc[i][7] + bl[7];
        *(float4*)(C + r * Nc + colBase + (tx << 3))     = o0;
        *(float4*)(C + r * Nc + colBase + (tx << 3) + 4) = o1;
    }
}

// ---------------------------------------------------------------------------
// Flash-style attention, fp32. One block = 64 queries of one (b,h) slice.
// Q/K/V are contiguous [1024,48] blocks inside the flat qkv buffer due to the
// reference's raw reshape. grid = (16 qtiles, 128 slices), 256 threads laid
// out as 16x16: thread (tx,ty) owns S rows ty*4+i, S cols tx & tx+16,
// O rows ty*4+i, O cols tx*3+j.
// ---------------------------------------------------------------------------
__global__ __launch_bounds__(256)
void attn_kernel(const float* __restrict__ qkv, float* __restrict__ ctx)
{
    __shared__ float Qs[64][52];   // stride 52: 16B-aligned rows for float4 reads
    __shared__ float Ks[32][49];   // stride 49: conflict-free col-strided reads
    __shared__ float Vs[32][49];
    __shared__ float Ps[64][33];

    const int tid = threadIdx.x;
    const int tx = tid & 15;
    const int ty = tid >> 4;
    const int slice = blockIdx.y;            // b*16 + h
    const int q0 = blockIdx.x << 6;

    const long base = (long)(slice >> 4) * HEAD_BLK + (long)(slice & 15) * SLICE_SZ;
    const float* Qg = qkv + base + (long)q0 * DH;
    const float* Kg = qkv + base + THIRD;
    const float* Vg = qkv + base + 2L * THIRD;

    // load Q tile (64x48), pre-scaled by 1/sqrt(dh)
    for (int idx = tid; idx < 64 * 12; idx += 256) {
        int n = idx / 12, dq = idx % 12;
        float4 v = *(const float4*)(Qg + n * 48 + dq * 4);
        Qs[n][dq * 4 + 0] = v.x * ATT_SCALE;
        Qs[n][dq * 4 + 1] = v.y * ATT_SCALE;
        Qs[n][dq * 4 + 2] = v.z * ATT_SCALE;
        Qs[n][dq * 4 + 3] = v.w * ATT_SCALE;
    }

    float m[4], l[4], accO[4][3];
    #pragma unroll
    for (int i = 0; i < 4; ++i) {
        m[i] = -INFINITY; l[i] = 0.f;
        accO[i][0] = accO[i][1] = accO[i][2] = 0.f;
    }

    for (int kt = 0; kt < NSEQ; kt += 32) {
        __syncthreads();   // protect Ks/Vs/Ps from previous iteration's readers
        for (int idx = tid; idx < 32 * 12; idx += 256) {
            int n = idx / 12, dq = idx % 12;
            float4 kv = *(const float4*)(Kg + (long)(kt + n) * 48 + dq * 4);
            float4 vv = *(const float4*)(Vg + (long)(kt + n) * 48 + dq * 4);
            Ks[n][dq * 4 + 0] = kv.x; Ks[n][dq * 4 + 1] = kv.y;
            Ks[n][dq * 4 + 2] = kv.z; Ks[n][dq * 4 + 3] = kv.w;
            Vs[n][dq * 4 + 0] = vv.x; Vs[n][dq * 4 + 1] = vv.y;
            Vs[n][dq * 4 + 2] = vv.z; Vs[n][dq * 4 + 3] = vv.w;
        }
        __syncthreads();

        // S = Qs @ Ks^T  (64x32 tile; this thread: rows 4ty+i, cols tx, tx+16)
        float accS[4][2];
        #pragma unroll
        for (int i = 0; i < 4; ++i) { accS[i][0] = 0.f; accS[i][1] = 0.f; }
        #pragma unroll
        for (int k4 = 0; k4 < 48; k4 += 4) {
            float qa[4][4];
            #pragma unroll
            for (int i = 0; i < 4; ++i) {
                float4 t = *(const float4*)&Qs[(ty << 2) + i][k4];
                qa[i][0] = t.x; qa[i][1] = t.y; qa[i][2] = t.z; qa[i][3] = t.w;
            }
            #pragma unroll
            for (int kk = 0; kk < 4; ++kk) {
                float k0v = Ks[tx][k4 + kk];
                float k1v = Ks[tx + 16][k4 + kk];
                #pragma unroll
                for (int i = 0; i < 4; ++i) {
                    accS[i][0] += qa[i][kk] * k0v;
                    accS[i][1] += qa[i][kk] * k1v;
                }
            }
        }

        // online softmax update (row reductions across the 16-lane half-warp)
        #pragma unroll
        for (int i = 0; i < 4; ++i) {
            float tm = fmaxf(accS[i][0], accS[i][1]);
            #pragma unroll
            for (int off = 8; off >= 1; off >>= 1)
                tm = fmaxf(tm, __shfl_xor_sync(0xffffffffu, tm, off));
            float mn = fmaxf(m[i], tm);
            float esc = __expf(m[i] - mn);
            m[i] = mn;
            float p0 = __expf(accS[i][0] - mn);
            float p1 = __expf(accS[i][1] - mn);
            float rs = p0 + p1;
            #pragma unroll
            for (int off = 8; off >= 1; off >>= 1)
                rs += __shfl_xor_sync(0xffffffffu, rs, off);
            l[i] = l[i] * esc + rs;
            accO[i][0] *= esc; accO[i][1] *= esc; accO[i][2] *= esc;
            Ps[(ty << 2) + i][tx]      = p0;
            Ps[(ty << 2) + i][tx + 16] = p1;
        }
        __syncthreads();

        // O += P @ V  (this thread: rows 4ty+i, cols 3tx+j)
        #pragma unroll 4
        for (int kk = 0; kk < 32; ++kk) {
            float v0 = Vs[kk][3 * tx + 0];
            float v1 = Vs[kk][3 * tx + 1];
            float v2 = Vs[kk][3 * tx + 2];
            #pragma unroll
            for (int i = 0; i < 4; ++i) {
                float pv = Ps[(ty << 2) + i][kk];
                accO[i][0] += pv * v0;
                accO[i][1] += pv * v1;
                accO[i][2] += pv * v2;
            }
        }
    }

    // write context in natural (b,h,n,d) layout -> flat view is [8192,768]
    float* out = ctx + base + (long)q0 * DH;
    #pragma unroll
    for (int i = 0; i < 4; ++i) {
        float inv = 1.0f / l[i];
        int r = (ty << 2) + i;
        out[r * 48 + 3 * tx + 0] = accO[i][0] * inv;
        out[r * 48 + 3 * tx + 1] = accO[i][1] * inv;
        out[r * 48 + 3 * tx + 2] = accO[i][2] * inv;
    }
}

// ---------------------------------------------------------------------------
extern "C" void kernel_launch(void* const* d_in, const int* in_sizes, int n_in,
                              void* d_out, int out_size)
{
    (void)in_sizes; (void)n_in; (void)out_size;
    const float* x    = (const float*)d_in[0];
    const float* Wqkv = (const float*)d_in[1];
    const float* Wo   = (const float*)d_in[2];
    const float* bo   = (const float*)d_in[3];
    float* out = (float*)d_out;

    void* qkvp = nullptr;
    void* ctxp = nullptr;
    cudaGetSymbolAddress(&qkvp, g_qkv);
    cudaGetSymbolAddress(&ctxp, g_ctx);

    // 1) QKV projection: [8192,768] @ [768,2304]
    sgemm_kernel<<<dim3(QKVC / 128, ROWS / 128), 256>>>(
        x, Wqkv, nullptr, (float*)qkvp, ROWS, QKVC, DIMM);

    // 2) attention per (b,h) slice
    attn_kernel<<<dim3(NSEQ / 64, NB * HEADS), 256>>>(
        (const float*)qkvp, (float*)ctxp);

    // 3) output projection: [8192,768] @ [768,768] + bias
    sgemm_kernel<<<dim3(DIMM / 128, ROWS / 128), 256>>>(
        (const float*)ctxp, Wo, bo, out, ROWS, DIMM, DIMM);
}

// round 3
// speedup vs baseline: 1.3762x; 1.3762x over previous
#include <cuda_runtime.h>
#include <cuda_bf16.h>
#include <math.h>
#include <stdint.h>

#define DIMM 768
#define HEADS 16
#define DH 48
#define NB 8
#define NSEQ 1024
#define ROWS 8192            // NB*NSEQ
#define QKVC 2304            // 3*DIMM
#define SLICE_SZ 49152       // NSEQ*DH
#define HEAD_BLK 786432      // HEADS*NSEQ*DH
#define THIRD 6291456        // NB*HEAD_BLK
#define ATT_SCALE 0.14433756729740643f  // 48^-0.5

// ---------------- scratch (__device__ globals; no allocation allowed) ------
__device__ float g_qkv[ROWS * QKVC];                 // fp32 qkv (attention input)
__device__ float g_ctx[ROWS * DIMM];                 // fp32 context
__device__ __nv_bfloat16 g_xhi[ROWS * DIMM];
__device__ __nv_bfloat16 g_xlo[ROWS * DIMM];
__device__ __nv_bfloat16 g_chi[ROWS * DIMM];
__device__ __nv_bfloat16 g_clo[ROWS * DIMM];
__device__ __nv_bfloat16 g_wqhi[QKVC * DIMM];        // Wqkv^T hi  [2304,768]
__device__ __nv_bfloat16 g_wqlo[QKVC * DIMM];
__device__ __nv_bfloat16 g_wohi[DIMM * DIMM];        // Wo^T hi    [768,768]
__device__ __nv_bfloat16 g_wolo[DIMM * DIMM];

// ---------------- PTX helpers (arch-agnostic: sm_80+ features only) --------
__device__ __forceinline__ uint32_t smem_u32(const void* p) {
    uint32_t a;
    asm("{ .reg .u64 t; cvta.to.shared.u64 t, %1; cvt.u32.u64 %0, t; }"
        : "=r"(a) : "l"(p));
    return a;
}
#define LDSM_X4(r0, r1, r2, r3, addr) \
    asm volatile("ldmatrix.sync.aligned.m8n8.x4.shared.b16 {%0,%1,%2,%3}, [%4];" \
                 : "=r"(r0), "=r"(r1), "=r"(r2), "=r"(r3) : "r"(addr))
#define LDSM_X2(r0, r1, addr) \
    asm volatile("ldmatrix.sync.aligned.m8n8.x2.shared.b16 {%0,%1}, [%2];" \
                 : "=r"(r0), "=r"(r1) : "r"(addr))
#define MMA_BF16(c, a, b) \
    asm volatile("mma.sync.aligned.m16n8k16.row.col.f32.bf16.bf16.f32 " \
                 "{%0,%1,%2,%3},{%4,%5,%6,%7},{%8,%9},{%0,%1,%2,%3};" \
                 : "+f"((c)[0]), "+f"((c)[1]), "+f"((c)[2]), "+f"((c)[3]) \
                 : "r"((a)[0]), "r"((a)[1]), "r"((a)[2]), "r"((a)[3]), \
                   "r"((b)[0]), "r"((b)[1]))
#define CP_ASYNC16(s, g) \
    asm volatile("cp.async.cg.shared.global [%0], [%1], 16;" :: "r"(s), "l"(g))
#define CP_COMMIT() asm volatile("cp.async.commit_group;" ::: "memory")
#define CP_WAIT1()  asm volatile("cp.async.wait_group 1;" ::: "memory")

// ---------------------------------------------------------------------------
// bf16x3 GEMM on mma.sync: C[M,Nc] = A[M,K] @ Bt[Nc,K]^T (+bias)
// A,Bt given as hi/lo bf16 pairs, K-major. BM=BN=128, BK=32, 256 threads,
// 8 warps (2x4), warp tile 64x32 (4x4 mma m16n8k16 tiles).
// Per (A,B) k16 step: Ahi*Bhi + Alo*Bhi + Ahi*Blo (lo*lo dropped).
// ---------------------------------------------------------------------------
#define BK 32
#define ROW_BYTES 80                       // 32 bf16 + 8 pad -> conflict-free
#define TILE_BYTES (128 * ROW_BYTES)       // 10240
#define STAGE_BYTES (4 * TILE_BYTES)       // Ahi,Alo,Bhi,Blo = 40960
#define GEMM_SMEM (2 * STAGE_BYTES)        // 81920

__device__ __forceinline__ void stage_load(
    uint32_t sbyte, const __nv_bfloat16* s0, const __nv_bfloat16* s1,
    const __nv_bfloat16* s2, const __nv_bfloat16* s3, int K, long kOff, int tid)
{
    const __nv_bfloat16* srcs[4] = {s0, s1, s2, s3};
    #pragma unroll
    for (int m = 0; m < 4; ++m) {
        #pragma unroll
        for (int t = 0; t < 2; ++t) {
            const int ch = tid * 2 + t;          // 0..511
            const int row = ch >> 2;
            const int cc = ch & 3;
            const void* g = srcs[m] + (long)row * K + kOff + cc * 8;
            uint32_t s = sbyte + m * TILE_BYTES + row * ROW_BYTES + cc * 16;
            CP_ASYNC16(s, g);
        }
    }
}

__global__ __launch_bounds__(256)
void mma_gemm(const __nv_bfloat16* __restrict__ Ahi, const __nv_bfloat16* __restrict__ Alo,
              const __nv_bfloat16* __restrict__ Bhi, const __nv_bfloat16* __restrict__ Blo,
              const float* __restrict__ bias, float* __restrict__ C,
              int M, int Nc, int K)
{
    extern __shared__ char smem[];
    const uint32_t sb = smem_u32(smem);
    const int tid = threadIdx.x;
    const int wid = tid >> 5;
    const int lane = tid & 31;
    const int wr = wid >> 2;                 // 0..1
    const int wc = wid & 3;                  // 0..3
    const int rowBase = blockIdx.y << 7;
    const int colBase = blockIdx.x << 7;
    const int nch = K / BK;                  // 24 for K=768

    const __nv_bfloat16* pAhi = Ahi + (long)rowBase * K;
    const __nv_bfloat16* pAlo = Alo + (long)rowBase * K;
    const __nv_bfloat16* pBhi = Bhi + (long)colBase * K;
    const __nv_bfloat16* pBlo = Blo + (long)colBase * K;

    // ldmatrix lane address components
    const int r8 = lane & 7;
    const int quad = lane >> 3;
    const int aRow = wr * 64 + (quad & 1) * 8 + r8;      // + i*16
    const int aColB = ((quad >> 1) * 8) * 2;             // + ks*32 bytes
    const int bRow = wc * 32 + (lane & 7);               // + j*8
    const int bColB = (((lane >> 3) & 1) * 8) * 2;       // + ks*32 bytes

    float acc[4][4][4];
    #pragma unroll
    for (int i = 0; i < 4; ++i)
        #pragma unroll
        for (int j = 0; j < 4; ++j)
            #pragma unroll
            for (int r = 0; r < 4; ++r) acc[i][j][r] = 0.f;

    // prologue
    stage_load(sb, pAhi, pAlo, pBhi, pBlo, K, 0, tid);
    CP_COMMIT();

    for (int c = 0; c < nch; ++c) {
        if (c + 1 < nch)
            stage_load(sb + ((c + 1) & 1) * STAGE_BYTES, pAhi, pAlo, pBhi, pBlo,
                       K, (long)(c + 1) * BK, tid);
        CP_COMMIT();
        CP_WAIT1();
        __syncthreads();

        const uint32_t stg = sb + (c & 1) * STAGE_BYTES;
        #pragma unroll
        for (int ks = 0; ks < 2; ++ks) {
            uint32_t ah[4][4], al[4][4];
            #pragma unroll
            for (int i = 0; i < 4; ++i) {
                uint32_t aoff = stg + (aRow + i * 16) * ROW_BYTES + aColB + ks * 32;
                LDSM_X4(ah[i][0], ah[i][1], ah[i][2], ah[i][3], aoff);
                LDSM_X4(al[i][0], al[i][1], al[i][2], al[i][3], aoff + TILE_BYTES);
            }
            uint32_t bh[4][2], bl[4][2];
            #pragma unroll
            for (int j = 0; j < 4; ++j) {
                uint32_t boff = stg + 2 * TILE_BYTES + (bRow + j * 8) * ROW_BYTES
                                + bColB + ks * 32;
                LDSM_X2(bh[j][0], bh[j][1], boff);
                LDSM_X2(bl[j][0], bl[j][1], boff + TILE_BYTES);
            }
            #pragma unroll
            for (int i = 0; i < 4; ++i)
                #pragma unroll
                for (int j = 0; j < 4; ++j) {
                    MMA_BF16(acc[i][j], ah[i], bh[j]);
                    MMA_BF16(acc[i][j], al[i], bh[j]);
                    MMA_BF16(acc[i][j], ah[i], bl[j]);
                }
        }
        __syncthreads();
    }

    // epilogue: accum layout: c0,c1 -> (row lane/4, col 2*(lane%4)+{0,1});
    //           c2,c3 -> row+8
    #pragma unroll
    for (int i = 0; i < 4; ++i) {
        const long r0 = rowBase + wr * 64 + i * 16 + (lane >> 2);
        #pragma unroll
        for (int j = 0; j < 4; ++j) {
            const int col = wc * 32 + j * 8 + (lane & 3) * 2;
            float b0 = 0.f, b1 = 0.f;
            if (bias != nullptr) {
                b0 = bias[colBase + col];
                b1 = bias[colBase + col + 1];
            }
            float2 v0 = make_float2(acc[i][j][0] + b0, acc[i][j][1] + b1);
            float2 v1 = make_float2(acc[i][j][2] + b0, acc[i][j][3] + b1);
            *(float2*)(C + r0 * Nc + colBase + col) = v0;
            *(float2*)(C + (r0 + 8) * Nc + colBase + col) = v1;
        }
    }
}

// ---------------------------------------------------------------------------
// prep: fp32 -> bf16 hi/lo split (elementwise)
// ---------------------------------------------------------------------------
__global__ __launch_bounds__(256)
void split_kernel(const float* __restrict__ src, __nv_bfloat16* __restrict__ hi,
                  __nv_bfloat16* __restrict__ lo, int n)
{
    int i = blockIdx.x * 256 + threadIdx.x;
    if (i < n) {
        float v = src[i];
        __nv_bfloat16 h = __float2bfloat16(v);
        hi[i] = h;
        lo[i] = __float2bfloat16(v - __bfloat162float(h));
    }
}

// prep: W[K,Nc] -> Wt[Nc,K] with hi/lo split
__global__ __launch_bounds__(256)
void tsplit_kernel(const float* __restrict__ W, __nv_bfloat16* __restrict__ Thi,
                   __nv_bfloat16* __restrict__ Tlo, int K, int Nc)
{
    __shared__ float t[32][33];
    const int n0 = blockIdx.x * 32;
    const int k0 = blockIdx.y * 32;
    const int lx = threadIdx.x & 31;
    const int ly = threadIdx.x >> 5;   // 0..7
    #pragma unroll
    for (int r = ly; r < 32; r += 8)
        t[r][lx] = W[(long)(k0 + r) * Nc + n0 + lx];
    __syncthreads();
    #pragma unroll
    for (int r = ly; r < 32; r += 8) {
        float v = t[lx][r];
        __nv_bfloat16 h = __float2bfloat16(v);
        long o = (long)(n0 + r) * K + k0 + lx;
        Thi[o] = h;
        Tlo[o] = __float2bfloat16(v - __bfloat162float(h));
    }
}

// ---------------------------------------------------------------------------
// Flash-style attention, fp32 (unchanged from R1).
// ---------------------------------------------------------------------------
__global__ __launch_bounds__(256)
void attn_kernel(const float* __restrict__ qkv, float* __restrict__ ctx)
{
    __shared__ float Qs[64][52];
    __shared__ float Ks[32][49];
    __shared__ float Vs[32][49];
    __shared__ float Ps[64][33];

    const int tid = threadIdx.x;
    const int tx = tid & 15;
    const int ty = tid >> 4;
    const int slice = blockIdx.y;
    const int q0 = blockIdx.x << 6;

    const long base = (long)(slice >> 4) * HEAD_BLK + (long)(slice & 15) * SLICE_SZ;
    const float* Qg = qkv + base + (long)q0 * DH;
    const float* Kg = qkv + base + THIRD;
    const float* Vg = qkv + base + 2L * THIRD;

    for (int idx = tid; idx < 64 * 12; idx += 256) {
        int n = idx / 12, dq = idx % 12;
        float4 v = *(const float4*)(Qg + n * 48 + dq * 4);
        Qs[n][dq * 4 + 0] = v.x * ATT_SCALE;
        Qs[n][dq * 4 + 1] = v.y * ATT_SCALE;
        Qs[n][dq * 4 + 2] = v.z * ATT_SCALE;
        Qs[n][dq * 4 + 3] = v.w * ATT_SCALE;
    }

    float m[4], l[4], accO[4][3];
    #pragma unroll
    for (int i = 0; i < 4; ++i) {
        m[i] = -INFINITY; l[i] = 0.f;
        accO[i][0] = accO[i][1] = accO[i][2] = 0.f;
    }

    for (int kt = 0; kt < NSEQ; kt += 32) {
        __syncthreads();
        for (int idx = tid; idx < 32 * 12; idx += 256) {
            int n = idx / 12, dq = idx % 12;
            float4 kv = *(const float4*)(Kg + (long)(kt + n) * 48 + dq * 4);
            float4 vv = *(const float4*)(Vg + (long)(kt + n) * 48 + dq * 4);
            Ks[n][dq * 4 + 0] = kv.x; Ks[n][dq * 4 + 1] = kv.y;
            Ks[n][dq * 4 + 2] = kv.z; Ks[n][dq * 4 + 3] = kv.w;
            Vs[n][dq * 4 + 0] = vv.x; Vs[n][dq * 4 + 1] = vv.y;
            Vs[n][dq * 4 + 2] = vv.z; Vs[n][dq * 4 + 3] = vv.w;
        }
        __syncthreads();

        float accS[4][2];
        #pragma unroll
        for (int i = 0; i < 4; ++i) { accS[i][0] = 0.f; accS[i][1] = 0.f; }
        #pragma unroll
        for (int k4 = 0; k4 < 48; k4 += 4) {
            float qa[4][4];
            #pragma unroll
            for (int i = 0; i < 4; ++i) {
                float4 t = *(const float4*)&Qs[(ty << 2) + i][k4];
                qa[i][0] = t.x; qa[i][1] = t.y; qa[i][2] = t.z; qa[i][3] = t.w;
            }
            #pragma unroll
            for (int kk = 0; kk < 4; ++kk) {
                float k0v = Ks[tx][k4 + kk];
                float k1v = Ks[tx + 16][k4 + kk];
                #pragma unroll
                for (int i = 0; i < 4; ++i) {
                    accS[i][0] += qa[i][kk] * k0v;
                    accS[i][1] += qa[i][kk] * k1v;
                }
            }
        }

        #pragma unroll
        for (int i = 0; i < 4; ++i) {
            float tm = fmaxf(accS[i][0], accS[i][1]);
            #pragma unroll
            for (int off = 8; off >= 1; off >>= 1)
                tm = fmaxf(tm, __shfl_xor_sync(0xffffffffu, tm, off));
            float mn = fmaxf(m[i], tm);
            float esc = __expf(m[i] - mn);
            m[i] = mn;
            float p0 = __expf(accS[i][0] - mn);
            float p1 = __expf(accS[i][1] - mn);
            float rs = p0 + p1;
            #pragma unroll
            for (int off = 8; off >= 1; off >>= 1)
                rs += __shfl_xor_sync(0xffffffffu, rs, off);
            l[i] = l[i] * esc + rs;
            accO[i][0] *= esc; accO[i][1] *= esc; accO[i][2] *= esc;
            Ps[(ty << 2) + i][tx]      = p0;
            Ps[(ty << 2) + i][tx + 16] = p1;
        }
        __syncthreads();

        #pragma unroll 4
        for (int kk = 0; kk < 32; ++kk) {
            float v0 = Vs[kk][3 * tx + 0];
            float v1 = Vs[kk][3 * tx + 1];
            float v2 = Vs[kk][3 * tx + 2];
            #pragma unroll
            for (int i = 0; i < 4; ++i) {
                float pv = Ps[(ty << 2) + i][kk];
                accO[i][0] += pv * v0;
                accO[i][1] += pv * v1;
                accO[i][2] += pv * v2;
            }
        }
    }

    float* out = ctx + base + (long)q0 * DH;
    #pragma unroll
    for (int i = 0; i < 4; ++i) {
        float inv = 1.0f / l[i];
        int r = (ty << 2) + i;
        out[r * 48 + 3 * tx + 0] = accO[i][0] * inv;
        out[r * 48 + 3 * tx + 1] = accO[i][1] * inv;
        out[r * 48 + 3 * tx + 2] = accO[i][2] * inv;
    }
}

// ---------------------------------------------------------------------------
extern "C" void kernel_launch(void* const* d_in, const int* in_sizes, int n_in,
                              void* d_out, int out_size)
{
    (void)in_sizes; (void)n_in; (void)out_size;
    const float* x    = (const float*)d_in[0];
    const float* Wqkv = (const float*)d_in[1];
    const float* Wo   = (const float*)d_in[2];
    const float* bo   = (const float*)d_in[3];
    float* out = (float*)d_out;

    void *qkvp, *ctxp, *xhi, *xlo, *chi, *clo, *wqhi, *wqlo, *wohi, *wolo;
    cudaGetSymbolAddress(&qkvp, g_qkv);
    cudaGetSymbolAddress(&ctxp, g_ctx);
    cudaGetSymbolAddress(&xhi, g_xhi);
    cudaGetSymbolAddress(&xlo, g_xlo);
    cudaGetSymbolAddress(&chi, g_chi);
    cudaGetSymbolAddress(&clo, g_clo);
    cudaGetSymbolAddress(&wqhi, g_wqhi);
    cudaGetSymbolAddress(&wqlo, g_wqlo);
    cudaGetSymbolAddress(&wohi, g_wohi);
    cudaGetSymbolAddress(&wolo, g_wolo);

    cudaFuncSetAttribute(mma_gemm, cudaFuncAttributeMaxDynamicSharedMemorySize,
                         GEMM_SMEM);

    // prep: split x, transpose+split weights
    split_kernel<<<(ROWS * DIMM + 255) / 256, 256>>>(
        x, (__nv_bfloat16*)xhi, (__nv_bfloat16*)xlo, ROWS * DIMM);
    tsplit_kernel<<<dim3(QKVC / 32, DIMM / 32), 256>>>(
        Wqkv, (__nv_bfloat16*)wqhi, (__nv_bfloat16*)wqlo, DIMM, QKVC);
    tsplit_kernel<<<dim3(DIMM / 32, DIMM / 32), 256>>>(
        Wo, (__nv_bfloat16*)wohi, (__nv_bfloat16*)wolo, DIMM, DIMM);

    // 1) QKV projection: [8192,768] @ [768,2304] via mma.sync bf16x3
    mma_gemm<<<dim3(QKVC / 128, ROWS / 128), 256, GEMM_SMEM>>>(
        (const __nv_bfloat16*)xhi, (const __nv_bfloat16*)xlo,
        (const __nv_bfloat16*)wqhi, (const __nv_bfloat16*)wqlo,
        nullptr, (float*)qkvp, ROWS, QKVC, DIMM);

    // 2) attention per (b,h) slice (fp32 SIMT)
    attn_kernel<<<dim3(NSEQ / 64, NB * HEADS), 256>>>(
        (const float*)qkvp, (float*)ctxp);

    // 3) split ctx, then output projection via mma.sync bf16x3 (+bias)
    split_kernel<<<(ROWS * DIMM + 255) / 256, 256>>>(
        (const float*)ctxp, (__nv_bfloat16*)chi, (__nv_bfloat16*)clo, ROWS * DIMM);
    mma_gemm<<<dim3(DIMM / 128, ROWS / 128), 256, GEMM_SMEM>>>(
        (const __nv_bfloat16*)chi, (const __nv_bfloat16*)clo,
        (const __nv_bfloat16*)wohi, (const __nv_bfloat16*)wolo,
        bo, out, ROWS, DIMM, DIMM);
}

// round 4
// speedup vs baseline: 2.5144x; 1.8271x over previous
#include <cuda_runtime.h>
#include <cuda_bf16.h>
#include <math.h>
#include <stdint.h>

#define DIMM 768
#define HEADS 16
#define DH 48
#define NB 8
#define NSEQ 1024
#define ROWS 8192            // NB*NSEQ
#define QKVC 2304            // 3*DIMM
#define SLICE_SZ 49152       // NSEQ*DH
#define HEAD_BLK 786432      // HEADS*NSEQ*DH
#define THIRD 6291456        // NB*HEAD_BLK
#define ATT_SCALE 0.14433756729740643f  // 48^-0.5

// ---------------- scratch (__device__ globals; no allocation allowed) ------
__device__ __nv_bfloat16 g_qkvhi[ROWS * QKVC];       // qkv hi  (GEMM1 out)
__device__ __nv_bfloat16 g_qkvlo[ROWS * QKVC];       // qkv lo
__device__ __nv_bfloat16 g_xhi[ROWS * DIMM];
__device__ __nv_bfloat16 g_xlo[ROWS * DIMM];
__device__ __nv_bfloat16 g_chi[ROWS * DIMM];         // context hi (attn out)
__device__ __nv_bfloat16 g_clo[ROWS * DIMM];
__device__ __nv_bfloat16 g_wqhi[QKVC * DIMM];        // Wqkv^T hi  [2304,768]
__device__ __nv_bfloat16 g_wqlo[QKVC * DIMM];
__device__ __nv_bfloat16 g_wohi[DIMM * DIMM];        // Wo^T hi    [768,768]
__device__ __nv_bfloat16 g_wolo[DIMM * DIMM];

// ---------------- PTX helpers (arch-agnostic: sm_80+ features only) --------
__device__ __forceinline__ uint32_t smem_u32(const void* p) {
    uint32_t a;
    asm("{ .reg .u64 t; cvta.to.shared.u64 t, %1; cvt.u32.u64 %0, t; }"
        : "=r"(a) : "l"(p));
    return a;
}
#define LDSM_X4(r0, r1, r2, r3, addr) \
    asm volatile("ldmatrix.sync.aligned.m8n8.x4.shared.b16 {%0,%1,%2,%3}, [%4];" \
                 : "=r"(r0), "=r"(r1), "=r"(r2), "=r"(r3) : "r"(addr))
#define LDSM_X2(r0, r1, addr) \
    asm volatile("ldmatrix.sync.aligned.m8n8.x2.shared.b16 {%0,%1}, [%2];" \
                 : "=r"(r0), "=r"(r1) : "r"(addr))
#define LDSM_X2T(r0, r1, addr) \
    asm volatile("ldmatrix.sync.aligned.m8n8.x2.trans.shared.b16 {%0,%1}, [%2];" \
                 : "=r"(r0), "=r"(r1) : "r"(addr))
#define MMA_BF16(c, a, b) \
    asm volatile("mma.sync.aligned.m16n8k16.row.col.f32.bf16.bf16.f32 " \
                 "{%0,%1,%2,%3},{%4,%5,%6,%7},{%8,%9},{%0,%1,%2,%3};" \
                 : "+f"((c)[0]), "+f"((c)[1]), "+f"((c)[2]), "+f"((c)[3]) \
                 : "r"((a)[0]), "r"((a)[1]), "r"((a)[2]), "r"((a)[3]), \
                   "r"((b)[0]), "r"((b)[1]))
#define CP_ASYNC16(s, g) \
    asm volatile("cp.async.cg.shared.global [%0], [%1], 16;" :: "r"(s), "l"(g))
#define CP_COMMIT() asm volatile("cp.async.commit_group;" ::: "memory")
#define CP_WAIT1()  asm volatile("cp.async.wait_group 1;" ::: "memory")

__device__ __forceinline__ uint32_t pack_hi(float a, float b, float& ra, float& rb) {
    __nv_bfloat162 t;
    t.x = __float2bfloat16(a);
    t.y = __float2bfloat16(b);
    ra = a - __bfloat162float(t.x);
    rb = b - __bfloat162float(t.y);
    return *(uint32_t*)&t;
}
__device__ __forceinline__ uint32_t pack2(float a, float b) {
    __nv_bfloat162 t;
    t.x = __float2bfloat16(a);
    t.y = __float2bfloat16(b);
    return *(uint32_t*)&t;
}

// ---------------------------------------------------------------------------
// bf16x3 GEMM on mma.sync: C = A @ Bt^T. BM=BN=128, BK=32, 8 warps.
// Output either fp32 (+bias) or bf16 hi/lo split pair.
// ---------------------------------------------------------------------------
#define BK 32
#define ROW_BYTES 80
#define TILE_BYTES (128 * ROW_BYTES)       // 10240
#define STAGE_BYTES (4 * TILE_BYTES)       // 40960
#define GEMM_SMEM (2 * STAGE_BYTES)        // 81920

__device__ __forceinline__ void stage_load(
    uint32_t sbyte, const __nv_bfloat16* s0, const __nv_bfloat16* s1,
    const __nv_bfloat16* s2, const __nv_bfloat16* s3, int K, long kOff, int tid)
{
    const __nv_bfloat16* srcs[4] = {s0, s1, s2, s3};
    #pragma unroll
    for (int m = 0; m < 4; ++m) {
        #pragma unroll
        for (int t = 0; t < 2; ++t) {
            const int ch = tid * 2 + t;
            const int row = ch >> 2;
            const int cc = ch & 3;
            const void* g = srcs[m] + (long)row * K + kOff + cc * 8;
            uint32_t s = sbyte + m * TILE_BYTES + row * ROW_BYTES + cc * 16;
            CP_ASYNC16(s, g);
        }
    }
}

__global__ __launch_bounds__(256)
void mma_gemm(const __nv_bfloat16* __restrict__ Ahi, const __nv_bfloat16* __restrict__ Alo,
              const __nv_bfloat16* __restrict__ Bhi, const __nv_bfloat16* __restrict__ Blo,
              const float* __restrict__ bias, float* __restrict__ C,
              __nv_bfloat16* __restrict__ Ohi, __nv_bfloat16* __restrict__ Olo,
              int M, int Nc, int K)
{
    extern __shared__ char smem[];
    const uint32_t sb = smem_u32(smem);
    const int tid = threadIdx.x;
    const int wid = tid >> 5;
    const int lane = tid & 31;
    const int wr = wid >> 2;
    const int wc = wid & 3;
    const int rowBase = blockIdx.y << 7;
    const int colBase = blockIdx.x << 7;
    const int nch = K / BK;

    const __nv_bfloat16* pAhi = Ahi + (long)rowBase * K;
    const __nv_bfloat16* pAlo = Alo + (long)rowBase * K;
    const __nv_bfloat16* pBhi = Bhi + (long)colBase * K;
    const __nv_bfloat16* pBlo = Blo + (long)colBase * K;

    const int r8 = lane & 7;
    const int quad = lane >> 3;
    const int aRow = wr * 64 + (quad & 1) * 8 + r8;
    const int aColB = ((quad >> 1) * 8) * 2;
    const int bRow = wc * 32 + (lane & 7);
    const int bColB = (((lane >> 3) & 1) * 8) * 2;

    float acc[4][4][4];
    #pragma unroll
    for (int i = 0; i < 4; ++i)
        #pragma unroll
        for (int j = 0; j < 4; ++j)
            #pragma unroll
            for (int r = 0; r < 4; ++r) acc[i][j][r] = 0.f;

    stage_load(sb, pAhi, pAlo, pBhi, pBlo, K, 0, tid);
    CP_COMMIT();

    for (int c = 0; c < nch; ++c) {
        if (c + 1 < nch)
            stage_load(sb + ((c + 1) & 1) * STAGE_BYTES, pAhi, pAlo, pBhi, pBlo,
                       K, (long)(c + 1) * BK, tid);
        CP_COMMIT();
        CP_WAIT1();
        __syncthreads();

        const uint32_t stg = sb + (c & 1) * STAGE_BYTES;
        #pragma unroll
        for (int ks = 0; ks < 2; ++ks) {
            uint32_t ah[4][4], al[4][4];
            #pragma unroll
            for (int i = 0; i < 4; ++i) {
                uint32_t aoff = stg + (aRow + i * 16) * ROW_BYTES + aColB + ks * 32;
                LDSM_X4(ah[i][0], ah[i][1], ah[i][2], ah[i][3], aoff);
                LDSM_X4(al[i][0], al[i][1], al[i][2], al[i][3], aoff + TILE_BYTES);
            }
            uint32_t bh[4][2], bl[4][2];
            #pragma unroll
            for (int j = 0; j < 4; ++j) {
                uint32_t boff = stg + 2 * TILE_BYTES + (bRow + j * 8) * ROW_BYTES
                                + bColB + ks * 32;
                LDSM_X2(bh[j][0], bh[j][1], boff);
                LDSM_X2(bl[j][0], bl[j][1], boff + TILE_BYTES);
            }
            #pragma unroll
            for (int i = 0; i < 4; ++i)
                #pragma unroll
                for (int j = 0; j < 4; ++j) {
                    MMA_BF16(acc[i][j], ah[i], bh[j]);
                    MMA_BF16(acc[i][j], al[i], bh[j]);
                    MMA_BF16(acc[i][j], ah[i], bl[j]);
                }
        }
        __syncthreads();
    }

    #pragma unroll
    for (int i = 0; i < 4; ++i) {
        const long r0 = rowBase + wr * 64 + i * 16 + (lane >> 2);
        #pragma unroll
        for (int j = 0; j < 4; ++j) {
            const int col = wc * 32 + j * 8 + (lane & 3) * 2;
            if (Ohi != nullptr) {
                float ra, rb;
                uint32_t h0 = pack_hi(acc[i][j][0], acc[i][j][1], ra, rb);
                *(uint32_t*)(Ohi + r0 * Nc + colBase + col) = h0;
                *(uint32_t*)(Olo + r0 * Nc + colBase + col) = pack2(ra, rb);
                uint32_t h1 = pack_hi(acc[i][j][2], acc[i][j][3], ra, rb);
                *(uint32_t*)(Ohi + (r0 + 8) * Nc + colBase + col) = h1;
                *(uint32_t*)(Olo + (r0 + 8) * Nc + colBase + col) = pack2(ra, rb);
            } else {
                float b0 = 0.f, b1 = 0.f;
                if (bias != nullptr) {
                    b0 = bias[colBase + col];
                    b1 = bias[colBase + col + 1];
                }
                *(float2*)(C + r0 * Nc + colBase + col) =
                    make_float2(acc[i][j][0] + b0, acc[i][j][1] + b1);
                *(float2*)(C + (r0 + 8) * Nc + colBase + col) =
                    make_float2(acc[i][j][2] + b0, acc[i][j][3] + b1);
            }
        }
    }
}

// ---------------------------------------------------------------------------
// prep kernels
// ---------------------------------------------------------------------------
__global__ __launch_bounds__(256)
void split_kernel(const float* __restrict__ src, __nv_bfloat16* __restrict__ hi,
                  __nv_bfloat16* __restrict__ lo, int n)
{
    int i = blockIdx.x * 256 + threadIdx.x;
    if (i < n) {
        float v = src[i];
        __nv_bfloat16 h = __float2bfloat16(v);
        hi[i] = h;
        lo[i] = __float2bfloat16(v - __bfloat162float(h));
    }
}

__global__ __launch_bounds__(256)
void tsplit_kernel(const float* __restrict__ W, __nv_bfloat16* __restrict__ Thi,
                   __nv_bfloat16* __restrict__ Tlo, int K, int Nc)
{
    __shared__ float t[32][33];
    const int n0 = blockIdx.x * 32;
    const int k0 = blockIdx.y * 32;
    const int lx = threadIdx.x & 31;
    const int ly = threadIdx.x >> 5;
    #pragma unroll
    for (int r = ly; r < 32; r += 8)
        t[r][lx] = W[(long)(k0 + r) * Nc + n0 + lx];
    __syncthreads();
    #pragma unroll
    for (int r = ly; r < 32; r += 8) {
        float v = t[lx][r];
        __nv_bfloat16 h = __float2bfloat16(v);
        long o = (long)(n0 + r) * K + k0 + lx;
        Thi[o] = h;
        Tlo[o] = __float2bfloat16(v - __bfloat162float(h));
    }
}

// ---------------------------------------------------------------------------
// Tensor-core flash attention. CTA = 128 queries of one (b,h) slice.
// 8 warps x 16 q-rows. Keys processed 64/tile, 16 tiles, double-buffered.
// QK and PV both bf16x3 (hi/lo split, lo*lo dropped).
// ---------------------------------------------------------------------------
#define AT_STRIDE 112                       // bytes per smem row (48 bf16 + pad)
#define AT_Q_BYTES (128 * AT_STRIDE)        // 14336
#define AT_T_BYTES (64 * AT_STRIDE)         // 7168
#define AT_STAGE (4 * AT_T_BYTES)           // 28672 (Khi,Klo,Vhi,Vlo)
#define ATT_SMEM (2 * AT_Q_BYTES + 2 * AT_STAGE)   // 86016

__device__ __forceinline__ void at_stage(
    uint32_t sdst, const __nv_bfloat16* kh, const __nv_bfloat16* kl,
    const __nv_bfloat16* vh, const __nv_bfloat16* vl, int key0, int tid)
{
    for (int i = tid; i < 384; i += 256) {
        const int r = i / 6, c = i % 6;
        const uint32_t off = r * AT_STRIDE + c * 16;
        const long gm = (long)(key0 + r) * DH + c * 8;
        CP_ASYNC16(sdst + off,                  kh + gm);
        CP_ASYNC16(sdst + AT_T_BYTES + off,     kl + gm);
        CP_ASYNC16(sdst + 2 * AT_T_BYTES + off, vh + gm);
        CP_ASYNC16(sdst + 3 * AT_T_BYTES + off, vl + gm);
    }
}

__global__ __launch_bounds__(256)
void attn_mma(const __nv_bfloat16* __restrict__ qkvhi,
              const __nv_bfloat16* __restrict__ qkvlo,
              __nv_bfloat16* __restrict__ Chi, __nv_bfloat16* __restrict__ Clo)
{
    extern __shared__ char smem[];
    const uint32_t sb = smem_u32(smem);
    const int tid = threadIdx.x;
    const int wid = tid >> 5;
    const int lane = tid & 31;
    const int slice = blockIdx.y;
    const int q0 = blockIdx.x << 7;

    const long base = (long)(slice >> 4) * HEAD_BLK + (long)(slice & 15) * SLICE_SZ;
    const __nv_bfloat16* qh = qkvhi + base + (long)q0 * DH;
    const __nv_bfloat16* ql = qkvlo + base + (long)q0 * DH;
    const __nv_bfloat16* kh = qkvhi + THIRD + base;
    const __nv_bfloat16* kl = qkvlo + THIRD + base;
    const __nv_bfloat16* vh = qkvhi + 2L * THIRD + base;
    const __nv_bfloat16* vl = qkvlo + 2L * THIRD + base;

    // group 0: Q tiles (hi+lo)
    for (int i = tid; i < 768; i += 256) {
        const int r = i / 6, c = i % 6;
        const uint32_t off = r * AT_STRIDE + c * 16;
        const long gm = (long)r * DH + c * 8;
        CP_ASYNC16(sb + off, qh + gm);
        CP_ASYNC16(sb + AT_Q_BYTES + off, ql + gm);
    }
    CP_COMMIT();
    // group 1: KV stage 0
    at_stage(sb + 2 * AT_Q_BYTES, kh, kl, vh, vl, 0, tid);
    CP_COMMIT();
    CP_WAIT1();          // Q ready
    __syncthreads();

    // Q fragments (kept in regs for whole kernel)
    uint32_t qhf[3][4], qlf[3][4];
    {
        const int aRow = wid * 16 + ((lane >> 3) & 1) * 8 + (lane & 7);
        const int aColB = (lane >> 4) * 16;
        #pragma unroll
        for (int ks = 0; ks < 3; ++ks) {
            uint32_t addr = sb + aRow * AT_STRIDE + aColB + ks * 32;
            LDSM_X4(qhf[ks][0], qhf[ks][1], qhf[ks][2], qhf[ks][3], addr);
            LDSM_X4(qlf[ks][0], qlf[ks][1], qlf[ks][2], qlf[ks][3], addr + AT_Q_BYTES);
        }
    }

    float m1 = -INFINITY, m2 = -INFINITY, l1 = 0.f, l2 = 0.f;
    float o[6][4];
    #pragma unroll
    for (int n = 0; n < 6; ++n)
        #pragma unroll
        for (int r = 0; r < 4; ++r) o[n][r] = 0.f;

    // frag address components
    const int kpair = lane >> 3;
    const int kRowOff = (kpair >> 1) * 8 + (lane & 7);
    const int kColB = (kpair & 1) * 16;
    const int vRowOff = (lane & 7) + ((lane >> 3) & 1) * 8;

    for (int kt = 0; kt < 16; ++kt) {
        if (kt + 1 < 16)
            at_stage(sb + 2 * AT_Q_BYTES + ((kt + 1) & 1) * AT_STAGE,
                     kh, kl, vh, vl, (kt + 1) * 64, tid);
        CP_COMMIT();
        CP_WAIT1();
        __syncthreads();

        const uint32_t stg = sb + 2 * AT_Q_BYTES + (kt & 1) * AT_STAGE;

        // ---- S = Q K^T (128x64 per CTA; this warp: 16x64) ----
        float s[8][4];
        #pragma unroll
        for (int j = 0; j < 8; ++j)
            #pragma unroll
            for (int r = 0; r < 4; ++r) s[j][r] = 0.f;

        #pragma unroll
        for (int g = 0; g < 4; ++g) {
            #pragma unroll
            for (int ks = 0; ks < 3; ++ks) {
                const uint32_t ka = stg + (g * 16 + kRowOff) * AT_STRIDE
                                    + kColB + ks * 32;
                uint32_t kb[4];
                LDSM_X4(kb[0], kb[1], kb[2], kb[3], ka);
                MMA_BF16(s[2 * g],     qhf[ks], kb);
                MMA_BF16(s[2 * g + 1], qhf[ks], kb + 2);
                MMA_BF16(s[2 * g],     qlf[ks], kb);
                MMA_BF16(s[2 * g + 1], qlf[ks], kb + 2);
                uint32_t kc[4];
                LDSM_X4(kc[0], kc[1], kc[2], kc[3], ka + AT_T_BYTES);
                MMA_BF16(s[2 * g],     qhf[ks], kc);
                MMA_BF16(s[2 * g + 1], qhf[ks], kc + 2);
            }
        }

        // ---- online softmax (rows r=lane>>2 and r+8 within warp tile) ----
        #pragma unroll
        for (int j = 0; j < 8; ++j)
            #pragma unroll
            for (int r = 0; r < 4; ++r) s[j][r] *= ATT_SCALE;

        float mx1 = s[0][0], mx2 = s[0][2];
        #pragma unroll
        for (int j = 0; j < 8; ++j) {
            mx1 = fmaxf(mx1, fmaxf(s[j][0], s[j][1]));
            mx2 = fmaxf(mx2, fmaxf(s[j][2], s[j][3]));
        }
        mx1 = fmaxf(mx1, __shfl_xor_sync(0xffffffffu, mx1, 1));
        mx1 = fmaxf(mx1, __shfl_xor_sync(0xffffffffu, mx1, 2));
        mx2 = fmaxf(mx2, __shfl_xor_sync(0xffffffffu, mx2, 1));
        mx2 = fmaxf(mx2, __shfl_xor_sync(0xffffffffu, mx2, 2));

        const float nm1 = fmaxf(m1, mx1);
        const float nm2 = fmaxf(m2, mx2);
        const float e1 = __expf(m1 - nm1);
        const float e2 = __expf(m2 - nm2);
        m1 = nm1; m2 = nm2;

        float sum1 = 0.f, sum2 = 0.f;
        #pragma unroll
        for (int j = 0; j < 8; ++j) {
            s[j][0] = __expf(s[j][0] - m1);
            s[j][1] = __expf(s[j][1] - m1);
            s[j][2] = __expf(s[j][2] - m2);
            s[j][3] = __expf(s[j][3] - m2);
            sum1 += s[j][0] + s[j][1];
            sum2 += s[j][2] + s[j][3];
        }
        sum1 += __shfl_xor_sync(0xffffffffu, sum1, 1);
        sum1 += __shfl_xor_sync(0xffffffffu, sum1, 2);
        sum2 += __shfl_xor_sync(0xffffffffu, sum2, 1);
        sum2 += __shfl_xor_sync(0xffffffffu, sum2, 2);
        l1 = l1 * e1 + sum1;
        l2 = l2 * e2 + sum2;

        #pragma unroll
        for (int n = 0; n < 6; ++n) {
            o[n][0] *= e1; o[n][1] *= e1;
            o[n][2] *= e2; o[n][3] *= e2;
        }

        // ---- O += P V ----
        #pragma unroll
        for (int kk = 0; kk < 4; ++kk) {
            uint32_t ph[4], pl[4];
            float ra, rb;
            ph[0] = pack_hi(s[2 * kk][0], s[2 * kk][1], ra, rb);
            pl[0] = pack2(ra, rb);
            ph[1] = pack_hi(s[2 * kk][2], s[2 * kk][3], ra, rb);
            pl[1] = pack2(ra, rb);
            ph[2] = pack_hi(s[2 * kk + 1][0], s[2 * kk + 1][1], ra, rb);
            pl[2] = pack2(ra, rb);
            ph[3] = pack_hi(s[2 * kk + 1][2], s[2 * kk + 1][3], ra, rb);
            pl[3] = pack2(ra, rb);

            const uint32_t vrowA = stg + 2 * AT_T_BYTES
                                   + (kk * 16 + vRowOff) * AT_STRIDE;
            #pragma unroll
            for (int n = 0; n < 6; ++n) {
                uint32_t vb[2], vc[2];
                LDSM_X2T(vb[0], vb[1], vrowA + n * 16);
                MMA_BF16(o[n], ph, vb);
                MMA_BF16(o[n], pl, vb);
                LDSM_X2T(vc[0], vc[1], vrowA + AT_T_BYTES + n * 16);
                MMA_BF16(o[n], ph, vc);
            }
        }
        __syncthreads();
    }

    // ---- epilogue: write context hi/lo at raw-reshape-flat offsets ----
    const float inv1 = 1.f / l1;
    const float inv2 = 1.f / l2;
    const long r1 = q0 + wid * 16 + (lane >> 2);
    const long r2 = r1 + 8;
    #pragma unroll
    for (int n = 0; n < 6; ++n) {
        const int col = n * 8 + (lane & 3) * 2;
        float ra, rb;
        uint32_t h0 = pack_hi(o[n][0] * inv1, o[n][1] * inv1, ra, rb);
        *(uint32_t*)(Chi + base + r1 * DH + col) = h0;
        *(uint32_t*)(Clo + base + r1 * DH + col) = pack2(ra, rb);
        uint32_t h1 = pack_hi(o[n][2] * inv2, o[n][3] * inv2, ra, rb);
        *(uint32_t*)(Chi + base + r2 * DH + col) = h1;
        *(uint32_t*)(Clo + base + r2 * DH + col) = pack2(ra, rb);
    }
}

// ---------------------------------------------------------------------------
extern "C" void kernel_launch(void* const* d_in, const int* in_sizes, int n_in,
                              void* d_out, int out_size)
{
    (void)in_sizes; (void)n_in; (void)out_size;
    const float* x    = (const float*)d_in[0];
    const float* Wqkv = (const float*)d_in[1];
    const float* Wo   = (const float*)d_in[2];
    const float* bo   = (const float*)d_in[3];
    float* out = (float*)d_out;

    void *qkvhi, *qkvlo, *xhi, *xlo, *chi, *clo, *wqhi, *wqlo, *wohi, *wolo;
    cudaGetSymbolAddress(&qkvhi, g_qkvhi);
    cudaGetSymbolAddress(&qkvlo, g_qkvlo);
    cudaGetSymbolAddress(&xhi, g_xhi);
    cudaGetSymbolAddress(&xlo, g_xlo);
    cudaGetSymbolAddress(&chi, g_chi);
    cudaGetSymbolAddress(&clo, g_clo);
    cudaGetSymbolAddress(&wqhi, g_wqhi);
    cudaGetSymbolAddress(&wqlo, g_wqlo);
    cudaGetSymbolAddress(&wohi, g_wohi);
    cudaGetSymbolAddress(&wolo, g_wolo);

    cudaFuncSetAttribute(mma_gemm, cudaFuncAttributeMaxDynamicSharedMemorySize,
                         GEMM_SMEM);
    cudaFuncSetAttribute(attn_mma, cudaFuncAttributeMaxDynamicSharedMemorySize,
                         ATT_SMEM);

    // prep
    split_kernel<<<(ROWS * DIMM + 255) / 256, 256>>>(
        x, (__nv_bfloat16*)xhi, (__nv_bfloat16*)xlo, ROWS * DIMM);
    tsplit_kernel<<<dim3(QKVC / 32, DIMM / 32), 256>>>(
        Wqkv, (__nv_bfloat16*)wqhi, (__nv_bfloat16*)wqlo, DIMM, QKVC);
    tsplit_kernel<<<dim3(DIMM / 32, DIMM / 32), 256>>>(
        Wo, (__nv_bfloat16*)wohi, (__nv_bfloat16*)wolo, DIMM, DIMM);

    // 1) QKV projection -> bf16 hi/lo qkv
    mma_gemm<<<dim3(QKVC / 128, ROWS / 128), 256, GEMM_SMEM>>>(
        (const __nv_bfloat16*)xhi, (const __nv_bfloat16*)xlo,
        (const __nv_bfloat16*)wqhi, (const __nv_bfloat16*)wqlo,
        nullptr, nullptr,
        (__nv_bfloat16*)qkvhi, (__nv_bfloat16*)qkvlo, ROWS, QKVC, DIMM);

    // 2) tensor-core flash attention -> context hi/lo
    attn_mma<<<dim3(NSEQ / 128, NB * HEADS), 256, ATT_SMEM>>>(
        (const __nv_bfloat16*)qkvhi, (const __nv_bfloat16*)qkvlo,
        (__nv_bfloat16*)chi, (__nv_bfloat16*)clo);

    // 3) output projection (+bias) -> fp32 out
    mma_gemm<<<dim3(DIMM / 128, ROWS / 128), 256, GEMM_SMEM>>>(
        (const __nv_bfloat16*)chi, (const __nv_bfloat16*)clo,
        (const __nv_bfloat16*)wohi, (const __nv_bfloat16*)wolo,
        bo, out, nullptr, nullptr, ROWS, DIMM, DIMM);
}

// round 6
// speedup vs baseline: 2.6723x; 1.0628x over previous
#include <cuda_runtime.h>
#include <cuda_bf16.h>
#include <math.h>
#include <stdint.h>

#define DIMM 768
#define HEADS 16
#define DH 48
#define NB 8
#define NSEQ 1024
#define ROWS 8192            // NB*NSEQ
#define QKVC 2304            // 3*DIMM
#define SLICE_SZ 49152       // NSEQ*DH
#define HEAD_BLK 786432      // HEADS*NSEQ*DH
#define THIRD 6291456        // NB*HEAD_BLK
#define ATT_SCALE 0.14433756729740643f  // 48^-0.5

// ---------------- scratch (__device__ globals; no allocation allowed) ------
__device__ __nv_bfloat16 g_qkvhi[ROWS * QKVC];       // qkv hi  (GEMM1 out)
__device__ __nv_bfloat16 g_qkvlo[ROWS * QKVC];       // qkv lo
__device__ __nv_bfloat16 g_xhi[ROWS * DIMM];
__device__ __nv_bfloat16 g_xlo[ROWS * DIMM];
__device__ __nv_bfloat16 g_chi[ROWS * DIMM];         // context hi (attn out)
__device__ __nv_bfloat16 g_clo[ROWS * DIMM];
__device__ __nv_bfloat16 g_wqhi[QKVC * DIMM];        // Wqkv^T hi  [2304,768]
__device__ __nv_bfloat16 g_wqlo[QKVC * DIMM];
__device__ __nv_bfloat16 g_wohi[DIMM * DIMM];        // Wo^T hi    [768,768]
__device__ __nv_bfloat16 g_wolo[DIMM * DIMM];

// ---------------- PTX helpers (arch-agnostic: sm_80+ features only) --------
__device__ __forceinline__ uint32_t smem_u32(const void* p) {
    uint32_t a;
    asm("{ .reg .u64 t; cvta.to.shared.u64 t, %1; cvt.u32.u64 %0, t; }"
        : "=r"(a) : "l"(p));
    return a;
}
#define LDSM_X4(r0, r1, r2, r3, addr) \
    asm volatile("ldmatrix.sync.aligned.m8n8.x4.shared.b16 {%0,%1,%2,%3}, [%4];" \
                 : "=r"(r0), "=r"(r1), "=r"(r2), "=r"(r3) : "r"(addr))
#define LDSM_X2(r0, r1, addr) \
    asm volatile("ldmatrix.sync.aligned.m8n8.x2.shared.b16 {%0,%1}, [%2];" \
                 : "=r"(r0), "=r"(r1) : "r"(addr))
#define LDSM_X2T(r0, r1, addr) \
    asm volatile("ldmatrix.sync.aligned.m8n8.x2.trans.shared.b16 {%0,%1}, [%2];" \
                 : "=r"(r0), "=r"(r1) : "r"(addr))
#define MMA_BF16(c, a, b) \
    asm volatile("mma.sync.aligned.m16n8k16.row.col.f32.bf16.bf16.f32 " \
                 "{%0,%1,%2,%3},{%4,%5,%6,%7},{%8,%9},{%0,%1,%2,%3};" \
                 : "+f"((c)[0]), "+f"((c)[1]), "+f"((c)[2]), "+f"((c)[3]) \
                 : "r"((a)[0]), "r"((a)[1]), "r"((a)[2]), "r"((a)[3]), \
                   "r"((b)[0]), "r"((b)[1]))
#define CP_ASYNC16(s, g) \
    asm volatile("cp.async.cg.shared.global [%0], [%1], 16;" :: "r"(s), "l"(g))
#define CP_COMMIT() asm volatile("cp.async.commit_group;" ::: "memory")
#define CP_WAIT1()  asm volatile("cp.async.wait_group 1;" ::: "memory")

__device__ __forceinline__ uint32_t pack_hi(float a, float b, float& ra, float& rb) {
    __nv_bfloat162 t;
    t.x = __float2bfloat16(a);
    t.y = __float2bfloat16(b);
    ra = a - __bfloat162float(t.x);
    rb = b - __bfloat162float(t.y);
    return *(uint32_t*)&t;
}
__device__ __forceinline__ uint32_t pack2(float a, float b) {
    __nv_bfloat162 t;
    t.x = __float2bfloat16(a);
    t.y = __float2bfloat16(b);
    return *(uint32_t*)&t;
}

// ---------------------------------------------------------------------------
// bf16x3 GEMM on mma.sync: C = A @ Bt^T. BM=BN=128, BK=32, 8 warps.
// Output either fp32 (+bias) or bf16 hi/lo split pair.
// __launch_bounds__(256, 2): cap at 128 regs so 2 CTAs/SM co-reside
// (R4 post-mortem: 133 regs -> 1 CTA/SM -> tensor pipe 55% -> 42%).
// ---------------------------------------------------------------------------
#define BK 32
#define ROW_BYTES 80
#define TILE_BYTES (128 * ROW_BYTES)       // 10240
#define STAGE_BYTES (4 * TILE_BYTES)       // 40960
#define GEMM_SMEM (2 * STAGE_BYTES)        // 81920

__device__ __forceinline__ void stage_load(
    uint32_t sbyte, const __nv_bfloat16* s0, const __nv_bfloat16* s1,
    const __nv_bfloat16* s2, const __nv_bfloat16* s3, int K, long kOff, int tid)
{
    const __nv_bfloat16* srcs[4] = {s0, s1, s2, s3};
    #pragma unroll
    for (int m = 0; m < 4; ++m) {
        #pragma unroll
        for (int t = 0; t < 2; ++t) {
            const int ch = tid * 2 + t;
            const int row = ch >> 2;
            const int cc = ch & 3;
            const void* g = srcs[m] + (long)row * K + kOff + cc * 8;
            uint32_t s = sbyte + m * TILE_BYTES + row * ROW_BYTES + cc * 16;
            CP_ASYNC16(s, g);
        }
    }
}

__global__ __launch_bounds__(256, 2)
void mma_gemm(const __nv_bfloat16* __restrict__ Ahi, const __nv_bfloat16* __restrict__ Alo,
              const __nv_bfloat16* __restrict__ Bhi, const __nv_bfloat16* __restrict__ Blo,
              const float* __restrict__ bias, float* __restrict__ C,
              __nv_bfloat16* __restrict__ Ohi, __nv_bfloat16* __restrict__ Olo,
              int M, int Nc, int K)
{
    extern __shared__ char smem[];
    const uint32_t sb = smem_u32(smem);
    const int tid = threadIdx.x;
    const int wid = tid >> 5;
    const int lane = tid & 31;
    const int wr = wid >> 2;
    const int wc = wid & 3;
    const int rowBase = blockIdx.y << 7;
    const int colBase = blockIdx.x << 7;
    const int nch = K / BK;

    const __nv_bfloat16* pAhi = Ahi + (long)rowBase * K;
    const __nv_bfloat16* pAlo = Alo + (long)rowBase * K;
    const __nv_bfloat16* pBhi = Bhi + (long)colBase * K;
    const __nv_bfloat16* pBlo = Blo + (long)colBase * K;

    const int r8 = lane & 7;
    const int quad = lane >> 3;
    const int aRow = wr * 64 + (quad & 1) * 8 + r8;
    const int aColB = ((quad >> 1) * 8) * 2;
    const int bRow = wc * 32 + (lane & 7);
    const int bColB = (((lane >> 3) & 1) * 8) * 2;

    float acc[4][4][4];
    #pragma unroll
    for (int i = 0; i < 4; ++i)
        #pragma unroll
        for (int j = 0; j < 4; ++j)
            #pragma unroll
            for (int r = 0; r < 4; ++r) acc[i][j][r] = 0.f;

    stage_load(sb, pAhi, pAlo, pBhi, pBlo, K, 0, tid);
    CP_COMMIT();

    for (int c = 0; c < nch; ++c) {
        if (c + 1 < nch)
            stage_load(sb + ((c + 1) & 1) * STAGE_BYTES, pAhi, pAlo, pBhi, pBlo,
                       K, (long)(c + 1) * BK, tid);
        CP_COMMIT();
        CP_WAIT1();
        __syncthreads();

        const uint32_t stg = sb + (c & 1) * STAGE_BYTES;
        #pragma unroll
        for (int ks = 0; ks < 2; ++ks) {
            uint32_t ah[4][4], al[4][4];
            #pragma unroll
            for (int i = 0; i < 4; ++i) {
                uint32_t aoff = stg + (aRow + i * 16) * ROW_BYTES + aColB + ks * 32;
                LDSM_X4(ah[i][0], ah[i][1], ah[i][2], ah[i][3], aoff);
                LDSM_X4(al[i][0], al[i][1], al[i][2], al[i][3], aoff + TILE_BYTES);
            }
            uint32_t bh[4][2], bl[4][2];
            #pragma unroll
            for (int j = 0; j < 4; ++j) {
                uint32_t boff = stg + 2 * TILE_BYTES + (bRow + j * 8) * ROW_BYTES
                                + bColB + ks * 32;
                LDSM_X2(bh[j][0], bh[j][1], boff);
                LDSM_X2(bl[j][0], bl[j][1], boff + TILE_BYTES);
            }
            #pragma unroll
            for (int i = 0; i < 4; ++i)
                #pragma unroll
                for (int j = 0; j < 4; ++j) {
                    MMA_BF16(acc[i][j], ah[i], bh[j]);
                    MMA_BF16(acc[i][j], al[i], bh[j]);
                    MMA_BF16(acc[i][j], ah[i], bl[j]);
                }
        }
        __syncthreads();
    }

    #pragma unroll
    for (int i = 0; i < 4; ++i) {
        const long r0 = rowBase + wr * 64 + i * 16 + (lane >> 2);
        #pragma unroll
        for (int j = 0; j < 4; ++j) {
            const int col = wc * 32 + j * 8 + (lane & 3) * 2;
            if (Ohi != nullptr) {
                float ra, rb;
                uint32_t h0 = pack_hi(acc[i][j][0], acc[i][j][1], ra, rb);
                *(uint32_t*)(Ohi + r0 * Nc + colBase + col) = h0;
                *(uint32_t*)(Olo + r0 * Nc + colBase + col) = pack2(ra, rb);
                uint32_t h1 = pack_hi(acc[i][j][2], acc[i][j][3], ra, rb);
                *(uint32_t*)(Ohi + (r0 + 8) * Nc + colBase + col) = h1;
                *(uint32_t*)(Olo + (r0 + 8) * Nc + colBase + col) = pack2(ra, rb);
            } else {
                float b0 = 0.f, b1 = 0.f;
                if (bias != nullptr) {
                    b0 = bias[colBase + col];
                    b1 = bias[colBase + col + 1];
                }
                *(float2*)(C + r0 * Nc + colBase + col) =
                    make_float2(acc[i][j][0] + b0, acc[i][j][1] + b1);
                *(float2*)(C + (r0 + 8) * Nc + colBase + col) =
                    make_float2(acc[i][j][2] + b0, acc[i][j][3] + b1);
            }
        }
    }
}

// ---------------------------------------------------------------------------
// prep kernels
// ---------------------------------------------------------------------------
__global__ __launch_bounds__(256)
void split_kernel(const float* __restrict__ src, __nv_bfloat16* __restrict__ hi,
                  __nv_bfloat16* __restrict__ lo, int n)
{
    int i = blockIdx.x * 256 + threadIdx.x;
    if (i < n) {
        float v = src[i];
        __nv_bfloat16 h = __float2bfloat16(v);
        hi[i] = h;
        lo[i] = __float2bfloat16(v - __bfloat162float(h));
    }
}

__global__ __launch_bounds__(256)
void tsplit_kernel(const float* __restrict__ W, __nv_bfloat16* __restrict__ Thi,
                   __nv_bfloat16* __restrict__ Tlo, int K, int Nc)
{
    __shared__ float t[32][33];
    const int n0 = blockIdx.x * 32;
    const int k0 = blockIdx.y * 32;
    const int lx = threadIdx.x & 31;
    const int ly = threadIdx.x >> 5;
    #pragma unroll
    for (int r = ly; r < 32; r += 8)
        t[r][lx] = W[(long)(k0 + r) * Nc + n0 + lx];
    __syncthreads();
    #pragma unroll
    for (int r = ly; r < 32; r += 8) {
        float v = t[lx][r];
        __nv_bfloat16 h = __float2bfloat16(v);
        long o = (long)(n0 + r) * K + k0 + lx;
        Thi[o] = h;
        Tlo[o] = __float2bfloat16(v - __bfloat162float(h));
    }
}

// ---------------------------------------------------------------------------
// Tensor-core flash attention. CTA = 128 queries of one (b,h) slice.
// 8 warps x 16 q-rows. Keys processed 64/tile, 16 tiles, double-buffered.
// QK and PV both bf16x3 (hi/lo split, lo*lo dropped).
// ---------------------------------------------------------------------------
#define AT_STRIDE 112                       // bytes per smem row (48 bf16 + pad)
#define AT_Q_BYTES (128 * AT_STRIDE)        // 14336
#define AT_T_BYTES (64 * AT_STRIDE)         // 7168
#define AT_STAGE (4 * AT_T_BYTES)           // 28672 (Khi,Klo,Vhi,Vlo)
#define ATT_SMEM (2 * AT_Q_BYTES + 2 * AT_STAGE)   // 86016

__device__ __forceinline__ void at_stage(
    uint32_t sdst, const __nv_bfloat16* kh, const __nv_bfloat16* kl,
    const __nv_bfloat16* vh, const __nv_bfloat16* vl, int key0, int tid)
{
    for (int i = tid; i < 384; i += 256) {
        const int r = i / 6, c = i % 6;
        const uint32_t off = r * AT_STRIDE + c * 16;
        const long gm = (long)(key0 + r) * DH + c * 8;
        CP_ASYNC16(sdst + off,                  kh + gm);
        CP_ASYNC16(sdst + AT_T_BYTES + off,     kl + gm);
        CP_ASYNC16(sdst + 2 * AT_T_BYTES + off, vh + gm);
        CP_ASYNC16(sdst + 3 * AT_T_BYTES + off, vl + gm);
    }
}

__global__ __launch_bounds__(256)
void attn_mma(const __nv_bfloat16* __restrict__ qkvhi,
              const __nv_bfloat16* __restrict__ qkvlo,
              __nv_bfloat16* __restrict__ Chi, __nv_bfloat16* __restrict__ Clo)
{
    extern __shared__ char smem[];
    const uint32_t sb = smem_u32(smem);
    const int tid = threadIdx.x;
    const int wid = tid >> 5;
    const int lane = tid & 31;
    const int slice = blockIdx.y;
    const int q0 = blockIdx.x << 7;

    const long base = (long)(slice >> 4) * HEAD_BLK + (long)(slice & 15) * SLICE_SZ;
    const __nv_bfloat16* qh = qkvhi + base + (long)q0 * DH;
    const __nv_bfloat16* ql = qkvlo + base + (long)q0 * DH;
    const __nv_bfloat16* kh = qkvhi + THIRD + base;
    const __nv_bfloat16* kl = qkvlo + THIRD + base;
    const __nv_bfloat16* vh = qkvhi + 2L * THIRD + base;
    const __nv_bfloat16* vl = qkvlo + 2L * THIRD + base;

    // group 0: Q tiles (hi+lo)
    for (int i = tid; i < 768; i += 256) {
        const int r = i / 6, c = i % 6;
        const uint32_t off = r * AT_STRIDE + c * 16;
        const long gm = (long)r * DH + c * 8;
        CP_ASYNC16(sb + off, qh + gm);
        CP_ASYNC16(sb + AT_Q_BYTES + off, ql + gm);
    }
    CP_COMMIT();
    // group 1: KV stage 0
    at_stage(sb + 2 * AT_Q_BYTES, kh, kl, vh, vl, 0, tid);
    CP_COMMIT();
    CP_WAIT1();          // Q ready
    __syncthreads();

    // Q fragments (kept in regs for whole kernel)
    uint32_t qhf[3][4], qlf[3][4];
    {
        const int aRow = wid * 16 + ((lane >> 3) & 1) * 8 + (lane & 7);
        const int aColB = (lane >> 4) * 16;
        #pragma unroll
        for (int ks = 0; ks < 3; ++ks) {
            uint32_t addr = sb + aRow * AT_STRIDE + aColB + ks * 32;
            LDSM_X4(qhf[ks][0], qhf[ks][1], qhf[ks][2], qhf[ks][3], addr);
            LDSM_X4(qlf[ks][0], qlf[ks][1], qlf[ks][2], qlf[ks][3], addr + AT_Q_BYTES);
        }
    }

    float m1 = -INFINITY, m2 = -INFINITY, l1 = 0.f, l2 = 0.f;
    float o[6][4];
    #pragma unroll
    for (int n = 0; n < 6; ++n)
        #pragma unroll
        for (int r = 0; r < 4; ++r) o[n][r] = 0.f;

    // frag address components
    const int kpair = lane >> 3;
    const int kRowOff = (kpair >> 1) * 8 + (lane & 7);
    const int kColB = (kpair & 1) * 16;
    const int vRowOff = (lane & 7) + ((lane >> 3) & 1) * 8;

    for (int kt = 0; kt < 16; ++kt) {
        if (kt + 1 < 16)
            at_stage(sb + 2 * AT_Q_BYTES + ((kt + 1) & 1) * AT_STAGE,
                     kh, kl, vh, vl, (kt + 1) * 64, tid);
        CP_COMMIT();
        CP_WAIT1();
        __syncthreads();

        const uint32_t stg = sb + 2 * AT_Q_BYTES + (kt & 1) * AT_STAGE;

        // ---- S = Q K^T (128x64 per CTA; this warp: 16x64) ----
        float s[8][4];
        #pragma unroll
        for (int j = 0; j < 8; ++j)
            #pragma unroll
            for (int r = 0; r < 4; ++r) s[j][r] = 0.f;

        #pragma unroll
        for (int g = 0; g < 4; ++g) {
            #pragma unroll
            for (int ks = 0; ks < 3; ++ks) {
                const uint32_t ka = stg + (g * 16 + kRowOff) * AT_STRIDE
                                    + kColB + ks * 32;
                uint32_t kb[4];
                LDSM_X4(kb[0], kb[1], kb[2], kb[3], ka);
                MMA_BF16(s[2 * g],     qhf[ks], kb);
                MMA_BF16(s[2 * g + 1], qhf[ks], kb + 2);
                MMA_BF16(s[2 * g],     qlf[ks], kb);
                MMA_BF16(s[2 * g + 1], qlf[ks], kb + 2);
                uint32_t kc[4];
                LDSM_X4(kc[0], kc[1], kc[2], kc[3], ka + AT_T_BYTES);
                MMA_BF16(s[2 * g],     qhf[ks], kc);
                MMA_BF16(s[2 * g + 1], qhf[ks], kc + 2);
            }
        }

        // ---- online softmax (rows r=lane>>2 and r+8 within warp tile) ----
        #pragma unroll
        for (int j = 0; j < 8; ++j)
            #pragma unroll
            for (int r = 0; r < 4; ++r) s[j][r] *= ATT_SCALE;

        float mx1 = s[0][0], mx2 = s[0][2];
        #pragma unroll
        for (int j = 0; j < 8; ++j) {
            mx1 = fmaxf(mx1, fmaxf(s[j][0], s[j][1]));
            mx2 = fmaxf(mx2, fmaxf(s[j][2], s[j][3]));
        }
        mx1 = fmaxf(mx1, __shfl_xor_sync(0xffffffffu, mx1, 1));
        mx1 = fmaxf(mx1, __shfl_xor_sync(0xffffffffu, mx1, 2));
        mx2 = fmaxf(mx2, __shfl_xor_sync(0xffffffffu, mx2, 1));
        mx2 = fmaxf(mx2, __shfl_xor_sync(0xffffffffu, mx2, 2));

        const float nm1 = fmaxf(m1, mx1);
        const float nm2 = fmaxf(m2, mx2);
        const float e1 = __expf(m1 - nm1);
        const float e2 = __expf(m2 - nm2);
        m1 = nm1; m2 = nm2;

        float sum1 = 0.f, sum2 = 0.f;
        #pragma unroll
        for (int j = 0; j < 8; ++j) {
            s[j][0] = __expf(s[j][0] - m1);
            s[j][1] = __expf(s[j][1] - m1);
            s[j][2] = __expf(s[j][2] - m2);
            s[j][3] = __expf(s[j][3] - m2);
            sum1 += s[j][0] + s[j][1];
            sum2 += s[j][2] + s[j][3];
        }
        sum1 += __shfl_xor_sync(0xffffffffu, sum1, 1);
        sum1 += __shfl_xor_sync(0xffffffffu, sum1, 2);
        sum2 += __shfl_xor_sync(0xffffffffu, sum2, 1);
        sum2 += __shfl_xor_sync(0xffffffffu, sum2, 2);
        l1 = l1 * e1 + sum1;
        l2 = l2 * e2 + sum2;

        #pragma unroll
        for (int n = 0; n < 6; ++n) {
            o[n][0] *= e1; o[n][1] *= e1;
            o[n][2] *= e2; o[n][3] *= e2;
        }

        // ---- O += P V ----
        #pragma unroll
        for (int kk = 0; kk < 4; ++kk) {
            uint32_t ph[4], pl[4];
            float ra, rb;
            ph[0] = pack_hi(s[2 * kk][0], s[2 * kk][1], ra, rb);
            pl[0] = pack2(ra, rb);
            ph[1] = pack_hi(s[2 * kk][2], s[2 * kk][3], ra, rb);
            pl[1] = pack2(ra, rb);
            ph[2] = pack_hi(s[2 * kk + 1][0], s[2 * kk + 1][1], ra, rb);
            pl[2] = pack2(ra, rb);
            ph[3] = pack_hi(s[2 * kk + 1][2], s[2 * kk + 1][3], ra, rb);
            pl[3] = pack2(ra, rb);

            const uint32_t vrowA = stg + 2 * AT_T_BYTES
                                   + (kk * 16 + vRowOff) * AT_STRIDE;
            #pragma unroll
            for (int n = 0; n < 6; ++n) {
                uint32_t vb[2], vc[2];
                LDSM_X2T(vb[0], vb[1], vrowA + n * 16);
                MMA_BF16(o[n], ph, vb);
                MMA_BF16(o[n], pl, vb);
                LDSM_X2T(vc[0], vc[1], vrowA + AT_T_BYTES + n * 16);
                MMA_BF16(o[n], ph, vc);
            }
        }
        __syncthreads();
    }

    // ---- epilogue: write context hi/lo at raw-reshape-flat offsets ----
    const float inv1 = 1.f / l1;
    const float inv2 = 1.f / l2;
    const long r1 = q0 + wid * 16 + (lane >> 2);
    const long r2 = r1 + 8;
    #pragma unroll
    for (int n = 0; n < 6; ++n) {
        const int col = n * 8 + (lane & 3) * 2;
        float ra, rb;
        uint32_t h0 = pack_hi(o[n][0] * inv1, o[n][1] * inv1, ra, rb);
        *(uint32_t*)(Chi + base + r1 * DH + col) = h0;
        *(uint32_t*)(Clo + base + r1 * DH + col) = pack2(ra, rb);
        uint32_t h1 = pack_hi(o[n][2] * inv2, o[n][3] * inv2, ra, rb);
        *(uint32_t*)(Chi + base + r2 * DH + col) = h1;
        *(uint32_t*)(Clo + base + r2 * DH + col) = pack2(ra, rb);
    }
}

// ---------------------------------------------------------------------------
extern "C" void kernel_launch(void* const* d_in, const int* in_sizes, int n_in,
                              void* d_out, int out_size)
{
    (void)in_sizes; (void)n_in; (void)out_size;
    const float* x    = (const float*)d_in[0];
    const float* Wqkv = (const float*)d_in[1];
    const float* Wo   = (const float*)d_in[2];
    const float* bo   = (const float*)d_in[3];
    float* out = (float*)d_out;

    void *qkvhi, *qkvlo, *xhi, *xlo, *chi, *clo, *wqhi, *wqlo, *wohi, *wolo;
    cudaGetSymbolAddress(&qkvhi, g_qkvhi);
    cudaGetSymbolAddress(&qkvlo, g_qkvlo);
    cudaGetSymbolAddress(&xhi, g_xhi);
    cudaGetSymbolAddress(&xlo, g_xlo);
    cudaGetSymbolAddress(&chi, g_chi);
    cudaGetSymbolAddress(&clo, g_clo);
    cudaGetSymbolAddress(&wqhi, g_wqhi);
    cudaGetSymbolAddress(&wqlo, g_wqlo);
    cudaGetSymbolAddress(&wohi, g_wohi);
    cudaGetSymbolAddress(&wolo, g_wolo);

    cudaFuncSetAttribute(mma_gemm, cudaFuncAttributeMaxDynamicSharedMemorySize,
                         GEMM_SMEM);
    cudaFuncSetAttribute(attn_mma, cudaFuncAttributeMaxDynamicSharedMemorySize,
                         ATT_SMEM);

    // prep
    split_kernel<<<(ROWS * DIMM + 255) / 256, 256>>>(
        x, (__nv_bfloat16*)xhi, (__nv_bfloat16*)xlo, ROWS * DIMM);
    tsplit_kernel<<<dim3(QKVC / 32, DIMM / 32), 256>>>(
        Wqkv, (__nv_bfloat16*)wqhi, (__nv_bfloat16*)wqlo, DIMM, QKVC);
    tsplit_kernel<<<dim3(DIMM / 32, DIMM / 32), 256>>>(
        Wo, (__nv_bfloat16*)wohi, (__nv_bfloat16*)wolo, DIMM, DIMM);

    // 1) QKV projection -> bf16 hi/lo qkv
    mma_gemm<<<dim3(QKVC / 128, ROWS / 128), 256, GEMM_SMEM>>>(
        (const __nv_bfloat16*)xhi, (const __nv_bfloat16*)xlo,
        (const __nv_bfloat16*)wqhi, (const __nv_bfloat16*)wqlo,
        nullptr, nullptr,
        (__nv_bfloat16*)qkvhi, (__nv_bfloat16*)qkvlo, ROWS, QKVC, DIMM);

    // 2) tensor-core flash attention -> context hi/lo
    attn_mma<<<dim3(NSEQ / 128, NB * HEADS), 256, ATT_SMEM>>>(
        (const __nv_bfloat16*)qkvhi, (const __nv_bfloat16*)qkvlo,
        (__nv_bfloat16*)chi, (__nv_bfloat16*)clo);

    // 3) output projection (+bias) -> fp32 out
    mma_gemm<<<dim3(DIMM / 128, ROWS / 128), 256, GEMM_SMEM>>>(
        (const __nv_bfloat16*)chi, (const __nv_bfloat16*)clo,
        (const __nv_bfloat16*)wohi, (const __nv_bfloat16*)wolo,
        bo, out, nullptr, nullptr, ROWS, DIMM, DIMM);
}

// round 8
// speedup vs baseline: 2.7731x; 1.0377x over previous
#include <cuda_runtime.h>
#include <cuda_bf16.h>
#include <math.h>
#include <stdint.h>

#define DIMM 768
#define HEADS 16
#define DH 48
#define NB 8
#define NSEQ 1024
#define ROWS 8192            // NB*NSEQ
#define QKVC 2304            // 3*DIMM
#define SLICE_SZ 49152       // NSEQ*DH
#define HEAD_BLK 786432      // HEADS*NSEQ*DH
#define THIRD 6291456        // NB*HEAD_BLK
#define ATT_SCALE 0.14433756729740643f  // 48^-0.5

// ---------------- scratch (__device__ globals; no allocation allowed) ------
__device__ __nv_bfloat16 g_qkvhi[ROWS * QKVC];       // qkv hi  (GEMM1 out)
__device__ __nv_bfloat16 g_qkvlo[ROWS * QKVC];       // qkv lo
__device__ __nv_bfloat16 g_xhi[ROWS * DIMM];
__device__ __nv_bfloat16 g_xlo[ROWS * DIMM];
__device__ __nv_bfloat16 g_chi[ROWS * DIMM];         // context hi (attn out)
__device__ __nv_bfloat16 g_clo[ROWS * DIMM];
__device__ __nv_bfloat16 g_wqhi[QKVC * DIMM];        // Wqkv^T hi  [2304,768]
__device__ __nv_bfloat16 g_wqlo[QKVC * DIMM];
__device__ __nv_bfloat16 g_wohi[DIMM * DIMM];        // Wo^T hi    [768,768]
__device__ __nv_bfloat16 g_wolo[DIMM * DIMM];

// ---------------- PTX helpers (arch-agnostic: sm_80+ features only) --------
__device__ __forceinline__ uint32_t smem_u32(const void* p) {
    uint32_t a;
    asm("{ .reg .u64 t; cvta.to.shared.u64 t, %1; cvt.u32.u64 %0, t; }"
        : "=r"(a) : "l"(p));
    return a;
}
#define LDSM_X4(r0, r1, r2, r3, addr) \
    asm volatile("ldmatrix.sync.aligned.m8n8.x4.shared.b16 {%0,%1,%2,%3}, [%4];" \
                 : "=r"(r0), "=r"(r1), "=r"(r2), "=r"(r3) : "r"(addr))
#define LDSM_X2(r0, r1, addr) \
    asm volatile("ldmatrix.sync.aligned.m8n8.x2.shared.b16 {%0,%1}, [%2];" \
                 : "=r"(r0), "=r"(r1) : "r"(addr))
#define LDSM_X2T(r0, r1, addr) \
    asm volatile("ldmatrix.sync.aligned.m8n8.x2.trans.shared.b16 {%0,%1}, [%2];" \
                 : "=r"(r0), "=r"(r1) : "r"(addr))
#define MMA_BF16(c, a, b) \
    asm volatile("mma.sync.aligned.m16n8k16.row.col.f32.bf16.bf16.f32 " \
                 "{%0,%1,%2,%3},{%4,%5,%6,%7},{%8,%9},{%0,%1,%2,%3};" \
                 : "+f"((c)[0]), "+f"((c)[1]), "+f"((c)[2]), "+f"((c)[3]) \
                 : "r"((a)[0]), "r"((a)[1]), "r"((a)[2]), "r"((a)[3]), \
                   "r"((b)[0]), "r"((b)[1]))
#define CP_ASYNC16(s, g) \
    asm volatile("cp.async.cg.shared.global [%0], [%1], 16;" :: "r"(s), "l"(g))
#define CP_COMMIT() asm volatile("cp.async.commit_group;" ::: "memory")
#define CP_WAIT1()  asm volatile("cp.async.wait_group 1;" ::: "memory")
#define CP_WAIT0()  asm volatile("cp.async.wait_group 0;" ::: "memory")

__device__ __forceinline__ uint32_t pack_hi(float a, float b, float& ra, float& rb) {
    __nv_bfloat162 t;
    t.x = __float2bfloat16(a);
    t.y = __float2bfloat16(b);
    ra = a - __bfloat162float(t.x);
    rb = b - __bfloat162float(t.y);
    return *(uint32_t*)&t;
}
__device__ __forceinline__ uint32_t pack2(float a, float b) {
    __nv_bfloat162 t;
    t.x = __float2bfloat16(a);
    t.y = __float2bfloat16(b);
    return *(uint32_t*)&t;
}

// ---------------------------------------------------------------------------
// bf16x3 GEMM on mma.sync: C = A @ Bt^T. BM=BN=128, BK=32, 8 warps.
// Correct single-barrier multistage schedule:
//   wait_group 0 -> __syncthreads -> issue next stage -> compute current.
// (wait+barrier before reads = cross-thread RAW safe; barrier after prior
//  compute = WAR safe on the freed buffer.)
// ---------------------------------------------------------------------------
#define BK 32
#define ROW_BYTES 80
#define TILE_BYTES (128 * ROW_BYTES)       // 10240
#define STAGE_BYTES (4 * TILE_BYTES)       // 40960
#define GEMM_SMEM (2 * STAGE_BYTES)        // 81920

__device__ __forceinline__ void stage_load(
    uint32_t sbyte, const __nv_bfloat16* s0, const __nv_bfloat16* s1,
    const __nv_bfloat16* s2, const __nv_bfloat16* s3, int K, long kOff, int tid)
{
    const __nv_bfloat16* srcs[4] = {s0, s1, s2, s3};
    #pragma unroll
    for (int m = 0; m < 4; ++m) {
        #pragma unroll
        for (int t = 0; t < 2; ++t) {
            const int ch = tid * 2 + t;
            const int row = ch >> 2;
            const int cc = ch & 3;
            const void* g = srcs[m] + (long)row * K + kOff + cc * 8;
            uint32_t s = sbyte + m * TILE_BYTES + row * ROW_BYTES + cc * 16;
            CP_ASYNC16(s, g);
        }
    }
}

__global__ __launch_bounds__(256, 2)
void mma_gemm(const __nv_bfloat16* __restrict__ Ahi, const __nv_bfloat16* __restrict__ Alo,
              const __nv_bfloat16* __restrict__ Bhi, const __nv_bfloat16* __restrict__ Blo,
              const float* __restrict__ bias, float* __restrict__ C,
              __nv_bfloat16* __restrict__ Ohi, __nv_bfloat16* __restrict__ Olo,
              int M, int Nc, int K)
{
    extern __shared__ char smem[];
    const uint32_t sb = smem_u32(smem);
    const int tid = threadIdx.x;
    const int wid = tid >> 5;
    const int lane = tid & 31;
    const int wr = wid >> 2;
    const int wc = wid & 3;
    const int rowBase = blockIdx.y << 7;
    const int colBase = blockIdx.x << 7;
    const int nch = K / BK;

    const __nv_bfloat16* pAhi = Ahi + (long)rowBase * K;
    const __nv_bfloat16* pAlo = Alo + (long)rowBase * K;
    const __nv_bfloat16* pBhi = Bhi + (long)colBase * K;
    const __nv_bfloat16* pBlo = Blo + (long)colBase * K;

    const int r8 = lane & 7;
    const int quad = lane >> 3;
    const int aRow = wr * 64 + (quad & 1) * 8 + r8;
    const int aColB = ((quad >> 1) * 8) * 2;
    const int bRow = wc * 32 + (lane & 7);
    const int bColB = (((lane >> 3) & 1) * 8) * 2;

    float acc[4][4][4];
    #pragma unroll
    for (int i = 0; i < 4; ++i)
        #pragma unroll
        for (int j = 0; j < 4; ++j)
            #pragma unroll
            for (int r = 0; r < 4; ++r) acc[i][j][r] = 0.f;

    // prologue: stage 0 in flight
    stage_load(sb, pAhi, pAlo, pBhi, pBlo, K, 0, tid);
    CP_COMMIT();

    for (int c = 0; c < nch; ++c) {
        CP_WAIT0();        // this thread's stage-c copies retired
        __syncthreads();   // all threads' data visible; compute c-1 done everywhere
        if (c + 1 < nch) { // buffer (c+1)&1 freed by the barrier above
            stage_load(sb + ((c + 1) & 1) * STAGE_BYTES, pAhi, pAlo, pBhi, pBlo,
                       K, (long)(c + 1) * BK, tid);
            CP_COMMIT();
        }

        const uint32_t stg = sb + (c & 1) * STAGE_BYTES;
        #pragma unroll
        for (int ks = 0; ks < 2; ++ks) {
            uint32_t ah[4][4], al[4][4];
            #pragma unroll
            for (int i = 0; i < 4; ++i) {
                uint32_t aoff = stg + (aRow + i * 16) * ROW_BYTES + aColB + ks * 32;
                LDSM_X4(ah[i][0], ah[i][1], ah[i][2], ah[i][3], aoff);
                LDSM_X4(al[i][0], al[i][1], al[i][2], al[i][3], aoff + TILE_BYTES);
            }
            uint32_t bh[4][2], bl[4][2];
            #pragma unroll
            for (int j = 0; j < 4; ++j) {
                uint32_t boff = stg + 2 * TILE_BYTES + (bRow + j * 8) * ROW_BYTES
                                + bColB + ks * 32;
                LDSM_X2(bh[j][0], bh[j][1], boff);
                LDSM_X2(bl[j][0], bl[j][1], boff + TILE_BYTES);
            }
            #pragma unroll
            for (int i = 0; i < 4; ++i)
                #pragma unroll
                for (int j = 0; j < 4; ++j) {
                    MMA_BF16(acc[i][j], ah[i], bh[j]);
                    MMA_BF16(acc[i][j], al[i], bh[j]);
                    MMA_BF16(acc[i][j], ah[i], bl[j]);
                }
        }
    }

    #pragma unroll
    for (int i = 0; i < 4; ++i) {
        const long r0 = rowBase + wr * 64 + i * 16 + (lane >> 2);
        #pragma unroll
        for (int j = 0; j < 4; ++j) {
            const int col = wc * 32 + j * 8 + (lane & 3) * 2;
            if (Ohi != nullptr) {
                float ra, rb;
                uint32_t h0 = pack_hi(acc[i][j][0], acc[i][j][1], ra, rb);
                *(uint32_t*)(Ohi + r0 * Nc + colBase + col) = h0;
                *(uint32_t*)(Olo + r0 * Nc + colBase + col) = pack2(ra, rb);
                uint32_t h1 = pack_hi(acc[i][j][2], acc[i][j][3], ra, rb);
                *(uint32_t*)(Ohi + (r0 + 8) * Nc + colBase + col) = h1;
                *(uint32_t*)(Olo + (r0 + 8) * Nc + colBase + col) = pack2(ra, rb);
            } else {
                float b0 = 0.f, b1 = 0.f;
                if (bias != nullptr) {
                    b0 = bias[colBase + col];
                    b1 = bias[colBase + col + 1];
                }
                *(float2*)(C + r0 * Nc + colBase + col) =
                    make_float2(acc[i][j][0] + b0, acc[i][j][1] + b1);
                *(float2*)(C + (r0 + 8) * Nc + colBase + col) =
                    make_float2(acc[i][j][2] + b0, acc[i][j][3] + b1);
            }
        }
    }
}

// ---------------------------------------------------------------------------
// prep kernels
// ---------------------------------------------------------------------------
__global__ __launch_bounds__(256)
void split_kernel(const float* __restrict__ src, __nv_bfloat16* __restrict__ hi,
                  __nv_bfloat16* __restrict__ lo, int n)
{
    int i = blockIdx.x * 256 + threadIdx.x;
    if (i < n) {
        float v = src[i];
        __nv_bfloat16 h = __float2bfloat16(v);
        hi[i] = h;
        lo[i] = __float2bfloat16(v - __bfloat162float(h));
    }
}

__global__ __launch_bounds__(256)
void tsplit_kernel(const float* __restrict__ W, __nv_bfloat16* __restrict__ Thi,
                   __nv_bfloat16* __restrict__ Tlo, int K, int Nc)
{
    __shared__ float t[32][33];
    const int n0 = blockIdx.x * 32;
    const int k0 = blockIdx.y * 32;
    const int lx = threadIdx.x & 31;
    const int ly = threadIdx.x >> 5;
    #pragma unroll
    for (int r = ly; r < 32; r += 8)
        t[r][lx] = W[(long)(k0 + r) * Nc + n0 + lx];
    __syncthreads();
    #pragma unroll
    for (int r = ly; r < 32; r += 8) {
        float v = t[lx][r];
        __nv_bfloat16 h = __float2bfloat16(v);
        long o = (long)(n0 + r) * K + k0 + lx;
        Thi[o] = h;
        Tlo[o] = __float2bfloat16(v - __bfloat162float(h));
    }
}

// ---------------------------------------------------------------------------
// Tensor-core flash attention. CTA = 128 queries of one (b,h) slice.
// 8 warps x 16 q-rows. Keys 64/tile, 16 tiles. Same corrected single-barrier
// multistage schedule as mma_gemm.
// ---------------------------------------------------------------------------
#define AT_STRIDE 112                       // bytes per smem row (48 bf16 + pad)
#define AT_Q_BYTES (128 * AT_STRIDE)        // 14336
#define AT_T_BYTES (64 * AT_STRIDE)         // 7168
#define AT_STAGE (4 * AT_T_BYTES)           // 28672 (Khi,Klo,Vhi,Vlo)
#define ATT_SMEM (2 * AT_Q_BYTES + 2 * AT_STAGE)   // 86016

__device__ __forceinline__ void at_stage(
    uint32_t sdst, const __nv_bfloat16* kh, const __nv_bfloat16* kl,
    const __nv_bfloat16* vh, const __nv_bfloat16* vl, int key0, int tid)
{
    for (int i = tid; i < 384; i += 256) {
        const int r = i / 6, c = i % 6;
        const uint32_t off = r * AT_STRIDE + c * 16;
        const long gm = (long)(key0 + r) * DH + c * 8;
        CP_ASYNC16(sdst + off,                  kh + gm);
        CP_ASYNC16(sdst + AT_T_BYTES + off,     kl + gm);
        CP_ASYNC16(sdst + 2 * AT_T_BYTES + off, vh + gm);
        CP_ASYNC16(sdst + 3 * AT_T_BYTES + off, vl + gm);
    }
}

__global__ __launch_bounds__(256)
void attn_mma(const __nv_bfloat16* __restrict__ qkvhi,
              const __nv_bfloat16* __restrict__ qkvlo,
              __nv_bfloat16* __restrict__ Chi, __nv_bfloat16* __restrict__ Clo)
{
    extern __shared__ char smem[];
    const uint32_t sb = smem_u32(smem);
    const int tid = threadIdx.x;
    const int wid = tid >> 5;
    const int lane = tid & 31;
    const int slice = blockIdx.y;
    const int q0 = blockIdx.x << 7;

    const long base = (long)(slice >> 4) * HEAD_BLK + (long)(slice & 15) * SLICE_SZ;
    const __nv_bfloat16* qh = qkvhi + base + (long)q0 * DH;
    const __nv_bfloat16* ql = qkvlo + base + (long)q0 * DH;
    const __nv_bfloat16* kh = qkvhi + THIRD + base;
    const __nv_bfloat16* kl = qkvlo + THIRD + base;
    const __nv_bfloat16* vh = qkvhi + 2L * THIRD + base;
    const __nv_bfloat16* vl = qkvlo + 2L * THIRD + base;

    // group 0: Q tiles (hi+lo)
    for (int i = tid; i < 768; i += 256) {
        const int r = i / 6, c = i % 6;
        const uint32_t off = r * AT_STRIDE + c * 16;
        const long gm = (long)r * DH + c * 8;
        CP_ASYNC16(sb + off, qh + gm);
        CP_ASYNC16(sb + AT_Q_BYTES + off, ql + gm);
    }
    CP_COMMIT();
    // group 1: KV stage 0
    at_stage(sb + 2 * AT_Q_BYTES, kh, kl, vh, vl, 0, tid);
    CP_COMMIT();
    CP_WAIT1();          // Q retired (this thread); stage 0 may be in flight
    __syncthreads();     // Q visible to all

    // Q fragments (kept in regs for whole kernel)
    uint32_t qhf[3][4], qlf[3][4];
    {
        const int aRow = wid * 16 + ((lane >> 3) & 1) * 8 + (lane & 7);
        const int aColB = (lane >> 4) * 16;
        #pragma unroll
        for (int ks = 0; ks < 3; ++ks) {
            uint32_t addr = sb + aRow * AT_STRIDE + aColB + ks * 32;
            LDSM_X4(qhf[ks][0], qhf[ks][1], qhf[ks][2], qhf[ks][3], addr);
            LDSM_X4(qlf[ks][0], qlf[ks][1], qlf[ks][2], qlf[ks][3], addr + AT_Q_BYTES);
        }
    }

    float m1 = -INFINITY, m2 = -INFINITY, l1 = 0.f, l2 = 0.f;
    float o[6][4];
    #pragma unroll
    for (int n = 0; n < 6; ++n)
        #pragma unroll
        for (int r = 0; r < 4; ++r) o[n][r] = 0.f;

    // frag address components
    const int kpair = lane >> 3;
    const int kRowOff = (kpair >> 1) * 8 + (lane & 7);
    const int kColB = (kpair & 1) * 16;
    const int vRowOff = (lane & 7) + ((lane >> 3) & 1) * 8;

    for (int kt = 0; kt < 16; ++kt) {
        CP_WAIT0();        // stage kt retired (this thread)
        __syncthreads();   // all threads' stage-kt data visible; compute kt-1 done
        if (kt + 1 < 16) { // stage buffer (kt+1)&1 freed by the barrier
            at_stage(sb + 2 * AT_Q_BYTES + ((kt + 1) & 1) * AT_STAGE,
                     kh, kl, vh, vl, (kt + 1) * 64, tid);
            CP_COMMIT();
        }

        const uint32_t stg = sb + 2 * AT_Q_BYTES + (kt & 1) * AT_STAGE;

        // ---- S = Q K^T (128x64 per CTA; this warp: 16x64) ----
        float s[8][4];
        #pragma unroll
        for (int j = 0; j < 8; ++j)
            #pragma unroll
            for (int r = 0; r < 4; ++r) s[j][r] = 0.f;

        #pragma unroll
        for (int g = 0; g < 4; ++g) {
            #pragma unroll
            for (int ks = 0; ks < 3; ++ks) {
                const uint32_t ka = stg + (g * 16 + kRowOff) * AT_STRIDE
                                    + kColB + ks * 32;
                uint32_t kb[4];
                LDSM_X4(kb[0], kb[1], kb[2], kb[3], ka);
                MMA_BF16(s[2 * g],     qhf[ks], kb);
                MMA_BF16(s[2 * g + 1], qhf[ks], kb + 2);
                MMA_BF16(s[2 * g],     qlf[ks], kb);
                MMA_BF16(s[2 * g + 1], qlf[ks], kb + 2);
                uint32_t kc[4];
                LDSM_X4(kc[0], kc[1], kc[2], kc[3], ka + AT_T_BYTES);
                MMA_BF16(s[2 * g],     qhf[ks], kc);
                MMA_BF16(s[2 * g + 1], qhf[ks], kc + 2);
            }
        }

        // ---- online softmax (rows r=lane>>2 and r+8 within warp tile) ----
        #pragma unroll
        for (int j = 0; j < 8; ++j)
            #pragma unroll
            for (int r = 0; r < 4; ++r) s[j][r] *= ATT_SCALE;

        float mx1 = s[0][0], mx2 = s[0][2];
        #pragma unroll
        for (int j = 0; j < 8; ++j) {
            mx1 = fmaxf(mx1, fmaxf(s[j][0], s[j][1]));
            mx2 = fmaxf(mx2, fmaxf(s[j][2], s[j][3]));
        }
        mx1 = fmaxf(mx1, __shfl_xor_sync(0xffffffffu, mx1, 1));
        mx1 = fmaxf(mx1, __shfl_xor_sync(0xffffffffu, mx1, 2));
        mx2 = fmaxf(mx2, __shfl_xor_sync(0xffffffffu, mx2, 1));
        mx2 = fmaxf(mx2, __shfl_xor_sync(0xffffffffu, mx2, 2));

        const float nm1 = fmaxf(m1, mx1);
        const float nm2 = fmaxf(m2, mx2);
        const float e1 = __expf(m1 - nm1);
        const float e2 = __expf(m2 - nm2);
        m1 = nm1; m2 = nm2;

        float sum1 = 0.f, sum2 = 0.f;
        #pragma unroll
        for (int j = 0; j < 8; ++j) {
            s[j][0] = __expf(s[j][0] - m1);
            s[j][1] = __expf(s[j][1] - m1);
            s[j][2] = __expf(s[j][2] - m2);
            s[j][3] = __expf(s[j][3] - m2);
            sum1 += s[j][0] + s[j][1];
            sum2 += s[j][2] + s[j][3];
        }
        sum1 += __shfl_xor_sync(0xffffffffu, sum1, 1);
        sum1 += __shfl_xor_sync(0xffffffffu, sum1, 2);
        sum2 += __shfl_xor_sync(0xffffffffu, sum2, 1);
        sum2 += __shfl_xor_sync(0xffffffffu, sum2, 2);
        l1 = l1 * e1 + sum1;
        l2 = l2 * e2 + sum2;

        #pragma unroll
        for (int n = 0; n < 6; ++n) {
            o[n][0] *= e1; o[n][1] *= e1;
            o[n][2] *= e2; o[n][3] *= e2;
        }

        // ---- O += P V ----
        #pragma unroll
        for (int kk = 0; kk < 4; ++kk) {
            uint32_t ph[4], pl[4];
            float ra, rb;
            ph[0] = pack_hi(s[2 * kk][0], s[2 * kk][1], ra, rb);
            pl[0] = pack2(ra, rb);
            ph[1] = pack_hi(s[2 * kk][2], s[2 * kk][3], ra, rb);
            pl[1] = pack2(ra, rb);
            ph[2] = pack_hi(s[2 * kk + 1][0], s[2 * kk + 1][1], ra, rb);
            pl[2] = pack2(ra, rb);
            ph[3] = pack_hi(s[2 * kk + 1][2], s[2 * kk + 1][3], ra, rb);
            pl[3] = pack2(ra, rb);

            const uint32_t vrowA = stg + 2 * AT_T_BYTES
                                   + (kk * 16 + vRowOff) * AT_STRIDE;
            #pragma unroll
            for (int n = 0; n < 6; ++n) {
                uint32_t vb[2], vc[2];
                LDSM_X2T(vb[0], vb[1], vrowA + n * 16);
                MMA_BF16(o[n], ph, vb);
                MMA_BF16(o[n], pl, vb);
                LDSM_X2T(vc[0], vc[1], vrowA + AT_T_BYTES + n * 16);
                MMA_BF16(o[n], ph, vc);
            }
        }
    }

    // ---- epilogue: write context hi/lo at raw-reshape-flat offsets ----
    const float inv1 = 1.f / l1;
    const float inv2 = 1.f / l2;
    const long r1 = q0 + wid * 16 + (lane >> 2);
    const long r2 = r1 + 8;
    #pragma unroll
    for (int n = 0; n < 6; ++n) {
        const int col = n * 8 + (lane & 3) * 2;
        float ra, rb;
        uint32_t h0 = pack_hi(o[n][0] * inv1, o[n][1] * inv1, ra, rb);
        *(uint32_t*)(Chi + base + r1 * DH + col) = h0;
        *(uint32_t*)(Clo + base + r1 * DH + col) = pack2(ra, rb);
        uint32_t h1 = pack_hi(o[n][2] * inv2, o[n][3] * inv2, ra, rb);
        *(uint32_t*)(Chi + base + r2 * DH + col) = h1;
        *(uint32_t*)(Clo + base + r2 * DH + col) = pack2(ra, rb);
    }
}

// ---------------------------------------------------------------------------
extern "C" void kernel_launch(void* const* d_in, const int* in_sizes, int n_in,
                              void* d_out, int out_size)
{
    (void)in_sizes; (void)n_in; (void)out_size;
    const float* x    = (const float*)d_in[0];
    const float* Wqkv = (const float*)d_in[1];
    const float* Wo   = (const float*)d_in[2];
    const float* bo   = (const float*)d_in[3];
    float* out = (float*)d_out;

    void *qkvhi, *qkvlo, *xhi, *xlo, *chi, *clo, *wqhi, *wqlo, *wohi, *wolo;
    cudaGetSymbolAddress(&qkvhi, g_qkvhi);
    cudaGetSymbolAddress(&qkvlo, g_qkvlo);
    cudaGetSymbolAddress(&xhi, g_xhi);
    cudaGetSymbolAddress(&xlo, g_xlo);
    cudaGetSymbolAddress(&chi, g_chi);
    cudaGetSymbolAddress(&clo, g_clo);
    cudaGetSymbolAddress(&wqhi, g_wqhi);
    cudaGetSymbolAddress(&wqlo, g_wqlo);
    cudaGetSymbolAddress(&wohi, g_wohi);
    cudaGetSymbolAddress(&wolo, g_wolo);

    cudaFuncSetAttribute(mma_gemm, cudaFuncAttributeMaxDynamicSharedMemorySize,
                         GEMM_SMEM);
    cudaFuncSetAttribute(attn_mma, cudaFuncAttributeMaxDynamicSharedMemorySize,
                         ATT_SMEM);

    // prep
    split_kernel<<<(ROWS * DIMM + 255) / 256, 256>>>(
        x, (__nv_bfloat16*)xhi, (__nv_bfloat16*)xlo, ROWS * DIMM);
    tsplit_kernel<<<dim3(QKVC / 32, DIMM / 32), 256>>>(
        Wqkv, (__nv_bfloat16*)wqhi, (__nv_bfloat16*)wqlo, DIMM, QKVC);
    tsplit_kernel<<<dim3(DIMM / 32, DIMM / 32), 256>>>(
        Wo, (__nv_bfloat16*)wohi, (__nv_bfloat16*)wolo, DIMM, DIMM);

    // 1) QKV projection -> bf16 hi/lo qkv
    mma_gemm<<<dim3(QKVC / 128, ROWS / 128), 256, GEMM_SMEM>>>(
        (const __nv_bfloat16*)xhi, (const __nv_bfloat16*)xlo,
        (const __nv_bfloat16*)wqhi, (const __nv_bfloat16*)wqlo,
        nullptr, nullptr,
        (__nv_bfloat16*)qkvhi, (__nv_bfloat16*)qkvlo, ROWS, QKVC, DIMM);

    // 2) tensor-core flash attention -> context hi/lo
    attn_mma<<<dim3(NSEQ / 128, NB * HEADS), 256, ATT_SMEM>>>(
        (const __nv_bfloat16*)qkvhi, (const __nv_bfloat16*)qkvlo,
        (__nv_bfloat16*)chi, (__nv_bfloat16*)clo);

    // 3) output projection (+bias) -> fp32 out
    mma_gemm<<<dim3(DIMM / 128, ROWS / 128), 256, GEMM_SMEM>>>(
        (const __nv_bfloat16*)chi, (const __nv_bfloat16*)clo,
        (const __nv_bfloat16*)wohi, (const __nv_bfloat16*)wolo,
        bo, out, nullptr, nullptr, ROWS, DIMM, DIMM);
}

// round 9
// speedup vs baseline: 3.8071x; 1.3729x over previous
#include <cuda_runtime.h>
#include <cuda_fp16.h>
#include <math.h>
#include <stdint.h>

#define DIMM 768
#define HEADS 16
#define DH 48
#define NB 8
#define NSEQ 1024
#define ROWS 8192            // NB*NSEQ
#define QKVC 2304            // 3*DIMM
#define SLICE_SZ 49152       // NSEQ*DH
#define HEAD_BLK 786432      // HEADS*NSEQ*DH
#define THIRD 6291456        // NB*HEAD_BLK
#define ATT_SCALE 0.14433756729740643f  // 48^-0.5

// ---------------- scratch (__device__ globals; no allocation allowed) ------
__device__ __half g_qkvhi[ROWS * QKVC];      // qkv hi  (GEMM1 out)
__device__ __half g_qkvlo[ROWS * QKVC];      // qkv lo  (only Q third written)
__device__ __half g_xhi[ROWS * DIMM];
__device__ __half g_xlo[ROWS * DIMM];
__device__ __half g_chi[ROWS * DIMM];        // context hi (attn out)
__device__ __half g_clo[ROWS * DIMM];
__device__ __half g_wqh[QKVC * DIMM];        // Wqkv^T fp16 [2304,768]
__device__ __half g_woh[DIMM * DIMM];        // Wo^T fp16   [768,768]

// ---------------- PTX helpers (arch-agnostic: sm_80+ features only) --------
__device__ __forceinline__ uint32_t smem_u32(const void* p) {
    uint32_t a;
    asm("{ .reg .u64 t; cvta.to.shared.u64 t, %1; cvt.u32.u64 %0, t; }"
        : "=r"(a) : "l"(p));
    return a;
}
#define LDSM_X4(r0, r1, r2, r3, addr) \
    asm volatile("ldmatrix.sync.aligned.m8n8.x4.shared.b16 {%0,%1,%2,%3}, [%4];" \
                 : "=r"(r0), "=r"(r1), "=r"(r2), "=r"(r3) : "r"(addr))
#define LDSM_X2(r0, r1, addr) \
    asm volatile("ldmatrix.sync.aligned.m8n8.x2.shared.b16 {%0,%1}, [%2];" \
                 : "=r"(r0), "=r"(r1) : "r"(addr))
#define LDSM_X2T(r0, r1, addr) \
    asm volatile("ldmatrix.sync.aligned.m8n8.x2.trans.shared.b16 {%0,%1}, [%2];" \
                 : "=r"(r0), "=r"(r1) : "r"(addr))
#define MMA_F16(c, a, b) \
    asm volatile("mma.sync.aligned.m16n8k16.row.col.f32.f16.f16.f32 " \
                 "{%0,%1,%2,%3},{%4,%5,%6,%7},{%8,%9},{%0,%1,%2,%3};" \
                 : "+f"((c)[0]), "+f"((c)[1]), "+f"((c)[2]), "+f"((c)[3]) \
                 : "r"((a)[0]), "r"((a)[1]), "r"((a)[2]), "r"((a)[3]), \
                   "r"((b)[0]), "r"((b)[1]))
#define CP_ASYNC16(s, g) \
    asm volatile("cp.async.cg.shared.global [%0], [%1], 16;" :: "r"(s), "l"(g))
#define CP_COMMIT() asm volatile("cp.async.commit_group;" ::: "memory")
#define CP_WAIT1()  asm volatile("cp.async.wait_group 1;" ::: "memory")
#define CP_WAIT0()  asm volatile("cp.async.wait_group 0;" ::: "memory")

__device__ __forceinline__ uint32_t packh_hi(float a, float b, float& ra, float& rb) {
    __half2 t;
    t.x = __float2half_rn(a);
    t.y = __float2half_rn(b);
    ra = a - __half2float(t.x);
    rb = b - __half2float(t.y);
    return *(uint32_t*)&t;
}
__device__ __forceinline__ uint32_t packh2(float a, float b) {
    __half2 t;
    t.x = __float2half_rn(a);
    t.y = __float2half_rn(b);
    return *(uint32_t*)&t;
}

// ---------------------------------------------------------------------------
// fp16 one-sided-split GEMM on mma.sync: C = (Ahi+Alo) @ B^T (+bias).
// BM=BN=128, BK=32, 8 warps, 3 tiles/stage (Ahi, Alo, B), 3-stage pipeline.
// Schedule per iter c:  wait(stage c done) -> barrier -> issue stage c+2
//                       -> compute stage c.
// ---------------------------------------------------------------------------
#define BK 32
#define ROW_BYTES 80
#define TILE_BYTES (128 * ROW_BYTES)       // 10240
#define STAGE_BYTES (3 * TILE_BYTES)       // 30720 (Ahi, Alo, B)
#define NSTAGE 3
#define GEMM_SMEM (NSTAGE * STAGE_BYTES)   // 92160

__device__ __forceinline__ void stage_load(
    uint32_t sbyte, const __half* s0, const __half* s1, const __half* s2,
    int K, long kOff, int tid)
{
    const __half* srcs[3] = {s0, s1, s2};
    #pragma unroll
    for (int m = 0; m < 3; ++m) {
        #pragma unroll
        for (int t = 0; t < 2; ++t) {
            const int ch = tid * 2 + t;          // 0..511
            const int row = ch >> 2;
            const int cc = ch & 3;
            const void* g = srcs[m] + (long)row * K + kOff + cc * 8;
            uint32_t s = sbyte + m * TILE_BYTES + row * ROW_BYTES + cc * 16;
            CP_ASYNC16(s, g);
        }
    }
}

__global__ __launch_bounds__(256, 2)
void mma_gemm(const __half* __restrict__ Ahi, const __half* __restrict__ Alo,
              const __half* __restrict__ B,
              const float* __restrict__ bias, float* __restrict__ C,
              __half* __restrict__ Ohi, __half* __restrict__ Olo,
              int loCols, int M, int Nc, int K)
{
    extern __shared__ char smem[];
    const uint32_t sb = smem_u32(smem);
    const int tid = threadIdx.x;
    const int wid = tid >> 5;
    const int lane = tid & 31;
    const int wr = wid >> 2;
    const int wc = wid & 3;
    const int rowBase = blockIdx.y << 7;
    const int colBase = blockIdx.x << 7;
    const int nch = K / BK;

    const __half* pAhi = Ahi + (long)rowBase * K;
    const __half* pAlo = Alo + (long)rowBase * K;
    const __half* pB   = B + (long)colBase * K;

    const int r8 = lane & 7;
    const int quad = lane >> 3;
    const int aRow = wr * 64 + (quad & 1) * 8 + r8;
    const int aColB = ((quad >> 1) * 8) * 2;
    const int bRow = wc * 32 + (lane & 7);
    const int bColB = (((lane >> 3) & 1) * 8) * 2;

    float acc[4][4][4];
    #pragma unroll
    for (int i = 0; i < 4; ++i)
        #pragma unroll
        for (int j = 0; j < 4; ++j)
            #pragma unroll
            for (int r = 0; r < 4; ++r) acc[i][j][r] = 0.f;

    // prologue: stages 0, 1 in flight
    stage_load(sb, pAhi, pAlo, pB, K, 0, tid);
    CP_COMMIT();
    stage_load(sb + STAGE_BYTES, pAhi, pAlo, pB, K, BK, tid);
    CP_COMMIT();

    for (int c = 0; c < nch; ++c) {
        if (c + 1 < nch) { CP_WAIT1(); } else { CP_WAIT0(); }  // stage c retired
        __syncthreads();   // stage-c visible to all; compute c-1 done everywhere
        if (c + 2 < nch) { // slot (c+2)%NSTAGE freed (last read at compute c-1)
            stage_load(sb + ((c + 2) % NSTAGE) * STAGE_BYTES, pAhi, pAlo, pB,
                       K, (long)(c + 2) * BK, tid);
            CP_COMMIT();
        }

        const uint32_t stg = sb + (c % NSTAGE) * STAGE_BYTES;
        #pragma unroll
        for (int ks = 0; ks < 2; ++ks) {
            uint32_t ah[4][4], al[4][4];
            #pragma unroll
            for (int i = 0; i < 4; ++i) {
                uint32_t aoff = stg + (aRow + i * 16) * ROW_BYTES + aColB + ks * 32;
                LDSM_X4(ah[i][0], ah[i][1], ah[i][2], ah[i][3], aoff);
                LDSM_X4(al[i][0], al[i][1], al[i][2], al[i][3], aoff + TILE_BYTES);
            }
            uint32_t bfr[4][2];
            #pragma unroll
            for (int j = 0; j < 4; ++j) {
                uint32_t boff = stg + 2 * TILE_BYTES + (bRow + j * 8) * ROW_BYTES
                                + bColB + ks * 32;
                LDSM_X2(bfr[j][0], bfr[j][1], boff);
            }
            // hi pass then lo pass: 16 independent chains each, no RAW stalls
            #pragma unroll
            for (int i = 0; i < 4; ++i)
                #pragma unroll
                for (int j = 0; j < 4; ++j)
                    MMA_F16(acc[i][j], ah[i], bfr[j]);
            #pragma unroll
            for (int i = 0; i < 4; ++i)
                #pragma unroll
                for (int j = 0; j < 4; ++j)
                    MMA_F16(acc[i][j], al[i], bfr[j]);
        }
    }

    #pragma unroll
    for (int i = 0; i < 4; ++i) {
        const long r0 = rowBase + wr * 64 + i * 16 + (lane >> 2);
        #pragma unroll
        for (int j = 0; j < 4; ++j) {
            const int col = wc * 32 + j * 8 + (lane & 3) * 2;
            if (Ohi != nullptr) {
                const bool wantLo = (colBase + col) < loCols;
                float ra, rb;
                uint32_t h0 = packh_hi(acc[i][j][0], acc[i][j][1], ra, rb);
                *(uint32_t*)(Ohi + r0 * Nc + colBase + col) = h0;
                if (wantLo)
                    *(uint32_t*)(Olo + r0 * Nc + colBase + col) = packh2(ra, rb);
                uint32_t h1 = packh_hi(acc[i][j][2], acc[i][j][3], ra, rb);
                *(uint32_t*)(Ohi + (r0 + 8) * Nc + colBase + col) = h1;
                if (wantLo)
                    *(uint32_t*)(Olo + (r0 + 8) * Nc + colBase + col) = packh2(ra, rb);
            } else {
                float b0 = 0.f, b1 = 0.f;
                if (bias != nullptr) {
                    b0 = bias[colBase + col];
                    b1 = bias[colBase + col + 1];
                }
                *(float2*)(C + r0 * Nc + colBase + col) =
                    make_float2(acc[i][j][0] + b0, acc[i][j][1] + b1);
                *(float2*)(C + (r0 + 8) * Nc + colBase + col) =
                    make_float2(acc[i][j][2] + b0, acc[i][j][3] + b1);
            }
        }
    }
}

// ---------------------------------------------------------------------------
// prep kernels
// ---------------------------------------------------------------------------
__global__ __launch_bounds__(256)
void split_kernel(const float* __restrict__ src, __half* __restrict__ hi,
                  __half* __restrict__ lo, int n)
{
    int i = blockIdx.x * 256 + threadIdx.x;
    if (i < n) {
        float v = src[i];
        __half h = __float2half_rn(v);
        hi[i] = h;
        lo[i] = __float2half_rn(v - __half2float(h));
    }
}

// W[K,Nc] -> W^T[Nc,K] single fp16
__global__ __launch_bounds__(256)
void tsingle_kernel(const float* __restrict__ W, __half* __restrict__ T,
                    int K, int Nc)
{
    __shared__ float t[32][33];
    const int n0 = blockIdx.x * 32;
    const int k0 = blockIdx.y * 32;
    const int lx = threadIdx.x & 31;
    const int ly = threadIdx.x >> 5;
    #pragma unroll
    for (int r = ly; r < 32; r += 8)
        t[r][lx] = W[(long)(k0 + r) * Nc + n0 + lx];
    __syncthreads();
    #pragma unroll
    for (int r = ly; r < 32; r += 8)
        T[(long)(n0 + r) * K + k0 + lx] = __float2half_rn(t[lx][r]);
}

// ---------------------------------------------------------------------------
// fp16 flash attention. CTA = 128 queries of one (b,h) slice. 8 warps.
// S = (Qhi+Qlo) K^T  (2 MMAs, K single fp16);  O += (Phi+Plo) V  (2 MMAs,
// V single fp16). Keys 64/tile, 16 tiles, double-buffered (R7 schedule).
// ---------------------------------------------------------------------------
#define AT_STRIDE 112                       // bytes per smem row (48 fp16 + pad)
#define AT_Q_BYTES (128 * AT_STRIDE)        // 14336
#define AT_T_BYTES (64 * AT_STRIDE)         // 7168
#define AT_STAGE (2 * AT_T_BYTES)           // 14336 (Khi, Vhi)
#define ATT_SMEM (2 * AT_Q_BYTES + 2 * AT_STAGE)   // 57344

__device__ __forceinline__ void at_stage(
    uint32_t sdst, const __half* kh, const __half* vh, int key0, int tid)
{
    for (int i = tid; i < 384; i += 256) {
        const int r = i / 6, c = i % 6;
        const uint32_t off = r * AT_STRIDE + c * 16;
        const long gm = (long)(key0 + r) * DH + c * 8;
        CP_ASYNC16(sdst + off,              kh + gm);
        CP_ASYNC16(sdst + AT_T_BYTES + off, vh + gm);
    }
}

__global__ __launch_bounds__(256)
void attn_mma(const __half* __restrict__ qkvhi, const __half* __restrict__ qkvlo,
              __half* __restrict__ Chi, __half* __restrict__ Clo)
{
    extern __shared__ char smem[];
    const uint32_t sb = smem_u32(smem);
    const int tid = threadIdx.x;
    const int wid = tid >> 5;
    const int lane = tid & 31;
    const int slice = blockIdx.y;
    const int q0 = blockIdx.x << 7;

    const long base = (long)(slice >> 4) * HEAD_BLK + (long)(slice & 15) * SLICE_SZ;
    const __half* qh = qkvhi + base + (long)q0 * DH;
    const __half* ql = qkvlo + base + (long)q0 * DH;
    const __half* kh = qkvhi + THIRD + base;
    const __half* vh = qkvhi + 2L * THIRD + base;

    // group 0: Q tiles (hi+lo)
    for (int i = tid; i < 768; i += 256) {
        const int r = i / 6, c = i % 6;
        const uint32_t off = r * AT_STRIDE + c * 16;
        const long gm = (long)r * DH + c * 8;
        CP_ASYNC16(sb + off, qh + gm);
        CP_ASYNC16(sb + AT_Q_BYTES + off, ql + gm);
    }
    CP_COMMIT();
    // group 1: KV stage 0
    at_stage(sb + 2 * AT_Q_BYTES, kh, vh, 0, tid);
    CP_COMMIT();
    CP_WAIT1();          // Q retired (this thread)
    __syncthreads();     // Q visible to all

    // Q fragments (kept in regs for whole kernel)
    uint32_t qhf[3][4], qlf[3][4];
    {
        const int aRow = wid * 16 + ((lane >> 3) & 1) * 8 + (lane & 7);
        const int aColB = (lane >> 4) * 16;
        #pragma unroll
        for (int ks = 0; ks < 3; ++ks) {
            uint32_t addr = sb + aRow * AT_STRIDE + aColB + ks * 32;
            LDSM_X4(qhf[ks][0], qhf[ks][1], qhf[ks][2], qhf[ks][3], addr);
            LDSM_X4(qlf[ks][0], qlf[ks][1], qlf[ks][2], qlf[ks][3], addr + AT_Q_BYTES);
        }
    }

    float m1 = -INFINITY, m2 = -INFINITY, l1 = 0.f, l2 = 0.f;
    float o[6][4];
    #pragma unroll
    for (int n = 0; n < 6; ++n)
        #pragma unroll
        for (int r = 0; r < 4; ++r) o[n][r] = 0.f;

    const int kpair = lane >> 3;
    const int kRowOff = (kpair >> 1) * 8 + (lane & 7);
    const int kColB = (kpair & 1) * 16;
    const int vRowOff = (lane & 7) + ((lane >> 3) & 1) * 8;

    for (int kt = 0; kt < 16; ++kt) {
        CP_WAIT0();        // stage kt retired (this thread)
        __syncthreads();   // stage-kt visible; compute kt-1 done everywhere
        if (kt + 1 < 16) {
            at_stage(sb + 2 * AT_Q_BYTES + ((kt + 1) & 1) * AT_STAGE,
                     kh, vh, (kt + 1) * 64, tid);
            CP_COMMIT();
        }

        const uint32_t stg = sb + 2 * AT_Q_BYTES + (kt & 1) * AT_STAGE;

        // ---- S = (Qhi+Qlo) K^T ----
        float s[8][4];
        #pragma unroll
        for (int j = 0; j < 8; ++j)
            #pragma unroll
            for (int r = 0; r < 4; ++r) s[j][r] = 0.f;

        #pragma unroll
        for (int g = 0; g < 4; ++g) {
            #pragma unroll
            for (int ks = 0; ks < 3; ++ks) {
                const uint32_t ka = stg + (g * 16 + kRowOff) * AT_STRIDE
                                    + kColB + ks * 32;
                uint32_t kb[4];
                LDSM_X4(kb[0], kb[1], kb[2], kb[3], ka);
                MMA_F16(s[2 * g],     qhf[ks], kb);
                MMA_F16(s[2 * g + 1], qhf[ks], kb + 2);
                MMA_F16(s[2 * g],     qlf[ks], kb);
                MMA_F16(s[2 * g + 1], qlf[ks], kb + 2);
            }
        }

        // ---- online softmax ----
        #pragma unroll
        for (int j = 0; j < 8; ++j)
            #pragma unroll
            for (int r = 0; r < 4; ++r) s[j][r] *= ATT_SCALE;

        float mx1 = s[0][0], mx2 = s[0][2];
        #pragma unroll
        for (int j = 0; j < 8; ++j) {
            mx1 = fmaxf(mx1, fmaxf(s[j][0], s[j][1]));
            mx2 = fmaxf(mx2, fmaxf(s[j][2], s[j][3]));
        }
        mx1 = fmaxf(mx1, __shfl_xor_sync(0xffffffffu, mx1, 1));
        mx1 = fmaxf(mx1, __shfl_xor_sync(0xffffffffu, mx1, 2));
        mx2 = fmaxf(mx2, __shfl_xor_sync(0xffffffffu, mx2, 1));
        mx2 = fmaxf(mx2, __shfl_xor_sync(0xffffffffu, mx2, 2));

        const float nm1 = fmaxf(m1, mx1);
        const float nm2 = fmaxf(m2, mx2);
        const float e1 = __expf(m1 - nm1);
        const float e2 = __expf(m2 - nm2);
        m1 = nm1; m2 = nm2;

        float sum1 = 0.f, sum2 = 0.f;
        #pragma unroll
        for (int j = 0; j < 8; ++j) {
            s[j][0] = __expf(s[j][0] - m1);
            s[j][1] = __expf(s[j][1] - m1);
            s[j][2] = __expf(s[j][2] - m2);
            s[j][3] = __expf(s[j][3] - m2);
            sum1 += s[j][0] + s[j][1];
            sum2 += s[j][2] + s[j][3];
        }
        sum1 += __shfl_xor_sync(0xffffffffu, sum1, 1);
        sum1 += __shfl_xor_sync(0xffffffffu, sum1, 2);
        sum2 += __shfl_xor_sync(0xffffffffu, sum2, 1);
        sum2 += __shfl_xor_sync(0xffffffffu, sum2, 2);
        l1 = l1 * e1 + sum1;
        l2 = l2 * e2 + sum2;

        #pragma unroll
        for (int n = 0; n < 6; ++n) {
            o[n][0] *= e1; o[n][1] *= e1;
            o[n][2] *= e2; o[n][3] *= e2;
        }

        // ---- O += (Phi+Plo) V ----
        #pragma unroll
        for (int kk = 0; kk < 4; ++kk) {
            uint32_t ph[4], pl[4];
            float ra, rb;
            ph[0] = packh_hi(s[2 * kk][0], s[2 * kk][1], ra, rb);
            pl[0] = packh2(ra, rb);
            ph[1] = packh_hi(s[2 * kk][2], s[2 * kk][3], ra, rb);
            pl[1] = packh2(ra, rb);
            ph[2] = packh_hi(s[2 * kk + 1][0], s[2 * kk + 1][1], ra, rb);
            pl[2] = packh2(ra, rb);
            ph[3] = packh_hi(s[2 * kk + 1][2], s[2 * kk + 1][3], ra, rb);
            pl[3] = packh2(ra, rb);

            const uint32_t vrowA = stg + AT_T_BYTES
                                   + (kk * 16 + vRowOff) * AT_STRIDE;
            #pragma unroll
            for (int n = 0; n < 6; ++n) {
                uint32_t vb[2];
                LDSM_X2T(vb[0], vb[1], vrowA + n * 16);
                MMA_F16(o[n], ph, vb);
                MMA_F16(o[n], pl, vb);
            }
        }
    }

    // ---- epilogue: write context hi/lo at raw-reshape-flat offsets ----
    const float inv1 = 1.f / l1;
    const float inv2 = 1.f / l2;
    const long r1 = q0 + wid * 16 + (lane >> 2);
    const long r2 = r1 + 8;
    #pragma unroll
    for (int n = 0; n < 6; ++n) {
        const int col = n * 8 + (lane & 3) * 2;
        float ra, rb;
        uint32_t h0 = packh_hi(o[n][0] * inv1, o[n][1] * inv1, ra, rb);
        *(uint32_t*)(Chi + base + r1 * DH + col) = h0;
        *(uint32_t*)(Clo + base + r1 * DH + col) = packh2(ra, rb);
        uint32_t h1 = packh_hi(o[n][2] * inv2, o[n][3] * inv2, ra, rb);
        *(uint32_t*)(Chi + base + r2 * DH + col) = h1;
        *(uint32_t*)(Clo + base + r2 * DH + col) = packh2(ra, rb);
    }
}

// ---------------------------------------------------------------------------
extern "C" void kernel_launch(void* const* d_in, const int* in_sizes, int n_in,
                              void* d_out, int out_size)
{
    (void)in_sizes; (void)n_in; (void)out_size;
    const float* x    = (const float*)d_in[0];
    const float* Wqkv = (const float*)d_in[1];
    const float* Wo   = (const float*)d_in[2];
    const float* bo   = (const float*)d_in[3];
    float* out = (float*)d_out;

    void *qkvhi, *qkvlo, *xhi, *xlo, *chi, *clo, *wqh, *woh;
    cudaGetSymbolAddress(&qkvhi, g_qkvhi);
    cudaGetSymbolAddress(&qkvlo, g_qkvlo);
    cudaGetSymbolAddress(&xhi, g_xhi);
    cudaGetSymbolAddress(&xlo, g_xlo);
    cudaGetSymbolAddress(&chi, g_chi);
    cudaGetSymbolAddress(&clo, g_clo);
    cudaGetSymbolAddress(&wqh, g_wqh);
    cudaGetSymbolAddress(&woh, g_woh);

    cudaFuncSetAttribute(mma_gemm, cudaFuncAttributeMaxDynamicSharedMemorySize,
                         GEMM_SMEM);
    cudaFuncSetAttribute(attn_mma, cudaFuncAttributeMaxDynamicSharedMemorySize,
                         ATT_SMEM);

    // prep: split x (hi/lo fp16), transpose weights to single fp16
    split_kernel<<<(ROWS * DIMM + 255) / 256, 256>>>(
        x, (__half*)xhi, (__half*)xlo, ROWS * DIMM);
    tsingle_kernel<<<dim3(QKVC / 32, DIMM / 32), 256>>>(
        Wqkv, (__half*)wqh, DIMM, QKVC);
    tsingle_kernel<<<dim3(DIMM / 32, DIMM / 32), 256>>>(
        Wo, (__half*)woh, DIMM, DIMM);

    // 1) QKV projection -> fp16 hi (all) / lo (Q third only)
    mma_gemm<<<dim3(QKVC / 128, ROWS / 128), 256, GEMM_SMEM>>>(
        (const __half*)xhi, (const __half*)xlo, (const __half*)wqh,
        nullptr, nullptr,
        (__half*)qkvhi, (__half*)qkvlo, DIMM /*loCols: Q third*/,
        ROWS, QKVC, DIMM);

    // 2) fp16 flash attention -> context hi/lo
    attn_mma<<<dim3(NSEQ / 128, NB * HEADS), 256, ATT_SMEM>>>(
        (const __half*)qkvhi, (const __half*)qkvlo,
        (__half*)chi, (__half*)clo);

    // 3) output projection (+bias) -> fp32 out
    mma_gemm<<<dim3(DIMM / 128, ROWS / 128), 256, GEMM_SMEM>>>(
        (const __half*)chi, (const __half*)clo, (const __half*)woh,
        bo, out, nullptr, nullptr, 0,
        ROWS, DIMM, DIMM);
}